// round 12
// baseline (speedup 1.0000x reference)
#include <cuda_runtime.h>
#include <cuda_bf16.h>
#include <math.h>
#include <stdint.h>

#define BATCH 2
#define SEQ   2048
#define DIM   512
#define NH    8
#define DH    64
#define NL    4
#define DFF   2048
#define WIN   256
#define BT    (BATCH*SEQ)   // 4096

// ---------------- scratch (static device globals; no allocation) -------------
__device__ float g_x [BT*DIM];
__device__ float g_q [BT*DIM];    // qkv partial q0 ; later Wo/W2 split-K partial 0
__device__ float g_k [BT*DIM];    // qkv partial k0 ; later Wo/W2 split-K partial 1
__device__ float g_v [BT*DIM];    // qkv partial v0
__device__ float g_q2[BT*DIM];    // qkv partial q1
__device__ float g_k2[BT*DIM];    // qkv partial k1
__device__ float g_v2[BT*DIM];    // qkv partial v1

__device__ __nv_bfloat16 g_xnh [BT*DIM];
__device__ __nv_bfloat16 g_xnl [BT*DIM];
__device__ __nv_bfloat16 g_atth[BT*DIM];
__device__ __nv_bfloat16 g_attl[BT*DIM];
__device__ __nv_bfloat16 g_hbh [BT*DFF];
__device__ __nv_bfloat16 g_hbl [BT*DFF];

// attention operands (pre-split)
__device__ __nv_bfloat16 g_qh [BT*DIM], g_ql [BT*DIM];
__device__ __nv_bfloat16 g_kh [BT*DIM], g_kl [BT*DIM];
__device__ __nv_bfloat16 g_vth[BT*DIM], g_vtl[BT*DIM];   // [b*512+d][SEQ]

// transposed split weights: [L][N][K]
__device__ __nv_bfloat16 g_wqt_h[NL*DIM*DIM],  g_wqt_l[NL*DIM*DIM];
__device__ __nv_bfloat16 g_wkt_h[NL*DIM*DIM],  g_wkt_l[NL*DIM*DIM];
__device__ __nv_bfloat16 g_wvt_h[NL*DIM*DIM],  g_wvt_l[NL*DIM*DIM];
__device__ __nv_bfloat16 g_wot_h[NL*DIM*DIM],  g_wot_l[NL*DIM*DIM];
__device__ __nv_bfloat16 g_w1t_h[NL*DIM*DFF],  g_w1t_l[NL*DIM*DFF];
__device__ __nv_bfloat16 g_w2t_h[NL*DFF*DIM],  g_w2t_l[NL*DFF*DIM];

// ---------------- PTX helpers --------------------------------------------------
__device__ __forceinline__ uint32_t smem_u32(const void* p) {
    uint32_t a;
    asm("{ .reg .u64 t; cvta.to.shared.u64 t, %1; cvt.u32.u64 %0, t; }"
        : "=r"(a) : "l"(p));
    return a;
}

__device__ __forceinline__ void cpa16(uint32_t dst, const void* src)
{
    asm volatile("cp.async.cg.shared.global [%0], [%1], 16;" :: "r"(dst), "l"(src));
}

__device__ __forceinline__ void ldmx4(uint32_t* r, uint32_t addr)
{
    asm volatile("ldmatrix.sync.aligned.m8n8.x4.shared.b16 {%0,%1,%2,%3}, [%4];"
        : "=r"(r[0]), "=r"(r[1]), "=r"(r[2]), "=r"(r[3]) : "r"(addr));
}

__device__ __forceinline__ void mma_bf16(float* c, const uint32_t* a, const uint32_t* b)
{
    asm volatile(
        "mma.sync.aligned.m16n8k16.row.col.f32.bf16.bf16.f32 "
        "{%0,%1,%2,%3}, {%4,%5,%6,%7}, {%8,%9}, {%0,%1,%2,%3};"
        : "+f"(c[0]), "+f"(c[1]), "+f"(c[2]), "+f"(c[3])
        : "r"(a[0]), "r"(a[1]), "r"(a[2]), "r"(a[3]), "r"(b[0]), "r"(b[1]));
}

__device__ __forceinline__ void split_bf16(float v, __nv_bfloat16& h, __nv_bfloat16& l)
{
    h = __float2bfloat16(v);
    l = __float2bfloat16(v - __bfloat162float(h));
}

// ---------------- mma.sync bf16-split GEMM (2-stage, 2 CTAs/SM) ----------------
#define TKC       32
#define RSTR      40
#define ARR_BYTES (128*RSTR*2)
#define STG_BYTES (4*ARR_BYTES)       // 40960
#define DSM_BYTES (2*STG_BYTES)       // 81920 -> 2 CTAs/SM

// Kstr = row stride of A/B (full K); kbase/Kloop select the k-range.
template <int GELU, int RES, int OUTF32, int OUTBF>
__device__ __forceinline__ void gemm_mm_core(
    const __nv_bfloat16* __restrict__ Ah, const __nv_bfloat16* __restrict__ Al,
    const __nv_bfloat16* __restrict__ Bh, const __nv_bfloat16* __restrict__ Bl,
    const float* __restrict__ bias, const float* __restrict__ res,
    float* __restrict__ C, __nv_bfloat16* __restrict__ Oh, __nv_bfloat16* __restrict__ Ol,
    int N, int Kstr, int kbase, int Kloop, int m0, int n0)
{
    extern __shared__ char dsm[];
    uint32_t sm0 = smem_u32(dsm);

    int tid  = threadIdx.x;
    int wid  = tid >> 5, lane = tid & 31;
    int mw   = (wid & 3) * 32;
    int nw   = (wid >> 2) * 64;

    float acc[2][8][4];
    #pragma unroll
    for (int i = 0; i < 2; i++)
        #pragma unroll
        for (int j = 0; j < 8; j++)
            #pragma unroll
            for (int t = 0; t < 4; t++) acc[i][j][t] = 0.f;

    int nk = Kloop / TKC;

    auto load_stage = [&](int c) {
        uint32_t sb = sm0 + (c & 1) * STG_BYTES;
        int k0 = kbase + c * TKC;
        #pragma unroll
        for (int it = 0; it < 8; it++) {
            int idx  = it * 256 + tid;
            int arr  = idx >> 9;
            int rem  = idx & 511;
            int row  = rem >> 2;
            int part = rem & 3;
            uint32_t dst = sb + arr * ARR_BYTES + row * (RSTR * 2) + part * 16;
            const __nv_bfloat16* src;
            if      (arr == 0) src = Ah + (size_t)(m0 + row) * Kstr + k0 + part * 8;
            else if (arr == 1) src = Al + (size_t)(m0 + row) * Kstr + k0 + part * 8;
            else if (arr == 2) src = Bh + (size_t)(n0 + row) * Kstr + k0 + part * 8;
            else               src = Bl + (size_t)(n0 + row) * Kstr + k0 + part * 8;
            cpa16(dst, src);
        }
        asm volatile("cp.async.commit_group;" ::: "memory");
    };

    load_stage(0);

    int a_row = mw + (lane & 15);
    int a_koff = (lane >> 4) * 8;
    int b_row = nw + (lane & 7) + ((lane >> 4) & 1) * 8;
    int b_koff = ((lane >> 3) & 1) * 8;

    for (int c = 0; c < nk; c++) {
        asm volatile("cp.async.wait_group 0;" ::: "memory");
        __syncthreads();

        if (c + 1 < nk) load_stage(c + 1);

        uint32_t sb  = sm0 + (c & 1) * STG_BYTES;
        uint32_t sah = sb;
        uint32_t sal = sb + ARR_BYTES;
        uint32_t sbh = sb + 2 * ARR_BYTES;
        uint32_t sbl = sb + 3 * ARR_BYTES;

        #pragma unroll
        for (int h = 0; h < 2; h++) {
            int k0 = h * 16;
            uint32_t ah[2][4], al[2][4];
            #pragma unroll
            for (int mt = 0; mt < 2; mt++) {
                uint32_t off = ((a_row + mt * 16) * RSTR + k0 + a_koff) * 2;
                ldmx4(ah[mt], sah + off);
                ldmx4(al[mt], sal + off);
            }
            #pragma unroll
            for (int ng = 0; ng < 4; ng++) {
                uint32_t bh[4], bl[4];
                uint32_t off = ((b_row + ng * 16) * RSTR + k0 + b_koff) * 2;
                ldmx4(bh, sbh + off);
                ldmx4(bl, sbl + off);
                #pragma unroll
                for (int mt = 0; mt < 2; mt++) {
                    mma_bf16(acc[mt][2*ng],   ah[mt], bh);
                    mma_bf16(acc[mt][2*ng],   ah[mt], bl);
                    mma_bf16(acc[mt][2*ng],   al[mt], bh);
                    mma_bf16(acc[mt][2*ng+1], ah[mt], bh + 2);
                    mma_bf16(acc[mt][2*ng+1], ah[mt], bl + 2);
                    mma_bf16(acc[mt][2*ng+1], al[mt], bh + 2);
                }
            }
        }
        __syncthreads();
    }

    int cbase_n = n0 + nw + (lane & 3) * 2;
    #pragma unroll
    for (int mt = 0; mt < 2; mt++) {
        #pragma unroll
        for (int half = 0; half < 2; half++) {
            int row = m0 + mw + mt * 16 + (lane >> 2) + half * 8;
            size_t rbase = (size_t)row * N;
            #pragma unroll
            for (int nt = 0; nt < 8; nt++) {
                int col = cbase_n + nt * 8;
                float v0 = acc[mt][nt][half * 2 + 0];
                float v1 = acc[mt][nt][half * 2 + 1];
                if (bias) {
                    float2 b2 = *reinterpret_cast<const float2*>(bias + col);
                    v0 += b2.x; v1 += b2.y;
                }
                if (GELU) {
                    v0 = 0.5f * v0 * (1.0f + erff(v0 * 0.70710678118654752f));
                    v1 = 0.5f * v1 * (1.0f + erff(v1 * 0.70710678118654752f));
                }
                if (RES) {
                    float2 r2 = *reinterpret_cast<const float2*>(res + rbase + col);
                    v0 += r2.x; v1 += r2.y;
                }
                if (OUTF32) {
                    *reinterpret_cast<float2*>(C + rbase + col) = make_float2(v0, v1);
                }
                if (OUTBF) {
                    __nv_bfloat16 h0, l0, h1, l1;
                    split_bf16(v0, h0, l0);
                    split_bf16(v1, h1, l1);
                    __nv_bfloat162 hh; hh.x = h0; hh.y = h1;
                    __nv_bfloat162 ll; ll.x = l0; ll.y = l1;
                    *reinterpret_cast<__nv_bfloat162*>(Oh + rbase + col) = hh;
                    *reinterpret_cast<__nv_bfloat162*>(Ol + rbase + col) = ll;
                }
            }
        }
    }
}

// plain GEMM (full K)
template <int GELU, int RES, int OUTF32, int OUTBF>
__global__ void __launch_bounds__(256, 2)
gemm_mm(const __nv_bfloat16* __restrict__ Ah, const __nv_bfloat16* __restrict__ Al,
        const __nv_bfloat16* __restrict__ Bh, const __nv_bfloat16* __restrict__ Bl,
        const float* __restrict__ bias, const float* __restrict__ res,
        float* __restrict__ C, __nv_bfloat16* __restrict__ Oh,
        __nv_bfloat16* __restrict__ Ol, int N, int K)
{
    gemm_mm_core<GELU, RES, OUTF32, OUTBF>(Ah, Al, Bh, Bl, bias, res, C, Oh, Ol,
                                           N, K, 0, K, blockIdx.y * 128, blockIdx.x * 128);
}

// split-K=2 GEMM: grid.z selects k-half; writes fp32 partial (bias only in half 0)
__global__ void __launch_bounds__(256, 2)
gemm_ksplit(const __nv_bfloat16* __restrict__ Ah, const __nv_bfloat16* __restrict__ Al,
            const __nv_bfloat16* __restrict__ Bh, const __nv_bfloat16* __restrict__ Bl,
            const float* __restrict__ bias,
            float* __restrict__ p0, float* __restrict__ p1, int N, int K)
{
    int kz = blockIdx.z;
    float* C = kz ? p1 : p0;
    const float* bi = kz ? nullptr : bias;
    gemm_mm_core<0, 0, 1, 0>(Ah, Al, Bh, Bl, bi, nullptr, C, nullptr, nullptr,
                             N, K, kz * (K / 2), K / 2,
                             blockIdx.y * 128, blockIdx.x * 128);
}

// fused QKV with split-K=2: grid.z = out*2 + khalf; 6 partial outputs
__global__ void __launch_bounds__(256, 2)
qkv_mm(const __nv_bfloat16* __restrict__ Ah, const __nv_bfloat16* __restrict__ Al,
       const __nv_bfloat16* __restrict__ Bqh, const __nv_bfloat16* __restrict__ Bql,
       const __nv_bfloat16* __restrict__ Bkh, const __nv_bfloat16* __restrict__ Bkl,
       const __nv_bfloat16* __restrict__ Bvh, const __nv_bfloat16* __restrict__ Bvl,
       const float* __restrict__ bq, const float* __restrict__ bk,
       const float* __restrict__ bv,
       float* __restrict__ q0, float* __restrict__ q1,
       float* __restrict__ k0, float* __restrict__ k1,
       float* __restrict__ v0, float* __restrict__ v1)
{
    int z  = blockIdx.z >> 1;
    int kz = blockIdx.z & 1;
    const __nv_bfloat16* Bh = (z == 0) ? Bqh : (z == 1) ? Bkh : Bvh;
    const __nv_bfloat16* Bl = (z == 0) ? Bql : (z == 1) ? Bkl : Bvl;
    const float* bi = kz ? nullptr : ((z == 0) ? bq : (z == 1) ? bk : bv);
    float* C = (z == 0) ? (kz ? q1 : q0)
             : (z == 1) ? (kz ? k1 : k0)
                        : (kz ? v1 : v0);
    gemm_mm_core<0, 0, 1, 0>(Ah, Al, Bh, Bl, bi, nullptr, C, nullptr, nullptr,
                             DIM, DIM, kz * (DIM / 2), DIM / 2,
                             blockIdx.y * 128, blockIdx.x * 128);
}

// ---------------- weight transpose + bf16 split -------------------------------
__global__ void wconv_kernel(const float* __restrict__ W,
                             __nv_bfloat16* __restrict__ hiT,
                             __nv_bfloat16* __restrict__ loT, int K, int N)
{
    __shared__ float t[32][33];
    int n0 = blockIdx.x * 32, k0 = blockIdx.y * 32;
    size_t lofs = (size_t)blockIdx.z * K * N;
    const float* Wl = W + lofs;
    int tx = threadIdx.x, ty = threadIdx.y;
    #pragma unroll
    for (int i = 0; i < 4; i++)
        t[ty + 8 * i][tx] = Wl[(size_t)(k0 + ty + 8 * i) * N + n0 + tx];
    __syncthreads();
    __nv_bfloat16* ho = hiT + lofs;
    __nv_bfloat16* lo = loT + lofs;
    #pragma unroll
    for (int i = 0; i < 4; i++) {
        float v = t[tx][ty + 8 * i];
        __nv_bfloat16 h, l;
        split_bf16(v, h, l);
        ho[(size_t)(n0 + ty + 8 * i) * K + k0 + tx] = h;
        lo[(size_t)(n0 + ty + 8 * i) * K + k0 + tx] = l;
    }
}

// ---------------- V transpose + split (folds v0+v1) ---------------------------
__global__ void vconv_kernel(const float* __restrict__ v0, const float* __restrict__ v1,
                             __nv_bfloat16* __restrict__ vth,
                             __nv_bfloat16* __restrict__ vtl)
{
    __shared__ float t[32][33];
    int t0 = blockIdx.x * 32, d0 = blockIdx.y * 32, b = blockIdx.z;
    int tx = threadIdx.x, ty = threadIdx.y;
    #pragma unroll
    for (int i = 0; i < 4; i++) {
        size_t idx = (size_t)(b * SEQ + t0 + ty + 8 * i) * DIM + d0 + tx;
        t[ty + 8 * i][tx] = v0[idx] + v1[idx];
    }
    __syncthreads();
    #pragma unroll
    for (int i = 0; i < 4; i++) {
        float val = t[tx][ty + 8 * i];
        __nv_bfloat16 h, l;
        split_bf16(val, h, l);
        size_t o = (size_t)(b * DIM + d0 + ty + 8 * i) * SEQ + t0 + tx;
        vth[o] = h;
        vtl[o] = l;
    }
}

// ---------------- RoPE + scale + split for q,k (folds partials) ---------------
__global__ void ropesplit_kernel(const float* __restrict__ q0, const float* __restrict__ q1,
                                 const float* __restrict__ k0, const float* __restrict__ k1,
                                 __nv_bfloat16* __restrict__ qh, __nv_bfloat16* __restrict__ ql,
                                 __nv_bfloat16* __restrict__ kh, __nv_bfloat16* __restrict__ kl)
{
    int idx = blockIdx.x * blockDim.x + threadIdx.x;   // over BT*NH*32
    int d  = idx & 31;
    int h  = (idx >> 5) & (NH - 1);
    int bt = idx >> 8;
    int t  = bt & (SEQ - 1);

    float inv_freq = __powf(10000.0f, -(float)(2 * d) / (float)DH);
    float ang = (float)t * inv_freq;
    float c, s;
    sincosf(ang, &s, &c);

    size_t base = (size_t)bt * DIM + h * DH + d;

    float qa = q0[base] + q1[base];
    float qb = q0[base + 32] + q1[base + 32];
    float qo1 = (qa * c - qb * s) * 0.125f;
    float qo2 = (qb * c + qa * s) * 0.125f;
    __nv_bfloat16 hh, ll;
    split_bf16(qo1, hh, ll); qh[base] = hh;      ql[base] = ll;
    split_bf16(qo2, hh, ll); qh[base + 32] = hh; ql[base + 32] = ll;

    float ka = k0[base] + k1[base];
    float kb = k0[base + 32] + k1[base + 32];
    float ko1 = ka * c - kb * s;
    float ko2 = kb * c + ka * s;
    split_bf16(ko1, hh, ll); kh[base] = hh;      kl[base] = ll;
    split_bf16(ko2, hh, ll); kh[base + 32] = hh; kl[base + 32] = ll;
}

// ---------------- LayerNorm (optionally folds split-K partials) ----------------
__global__ void ln_kernel(const float* __restrict__ x,
                          const float* __restrict__ p0, const float* __restrict__ p1,
                          const float* __restrict__ g, const float* __restrict__ b,
                          float* __restrict__ xout, float* __restrict__ y,
                          __nv_bfloat16* __restrict__ yh, __nv_bfloat16* __restrict__ yl)
{
    int row = blockIdx.x;
    int tid = threadIdx.x;
    size_t base = (size_t)row * DIM;

    float v0 = x[base + tid];
    float v1 = x[base + tid + 256];
    if (p0) {
        v0 += p0[base + tid] + p1[base + tid];
        v1 += p0[base + tid + 256] + p1[base + tid + 256];
    }
    if (xout) {
        xout[base + tid]       = v0;
        xout[base + tid + 256] = v1;
    }

    float s  = v0 + v1;
    float ss = v0 * v0 + v1 * v1;
    #pragma unroll
    for (int o = 16; o; o >>= 1) {
        s  += __shfl_xor_sync(0xffffffffu, s,  o);
        ss += __shfl_xor_sync(0xffffffffu, ss, o);
    }
    __shared__ float ws[8], wss[8];
    int w = tid >> 5, ln = tid & 31;
    if (ln == 0) { ws[w] = s; wss[w] = ss; }
    __syncthreads();
    __shared__ float s_mu, s_rstd;
    if (tid == 0) {
        float S = 0.f, SS = 0.f;
        #pragma unroll
        for (int i = 0; i < 8; i++) { S += ws[i]; SS += wss[i]; }
        float mu  = S * (1.0f / DIM);
        float var = SS * (1.0f / DIM) - mu * mu;
        s_mu = mu; s_rstd = rsqrtf(var + 1e-5f);
    }
    __syncthreads();
    float mu = s_mu, rstd = s_rstd;
    float o0 = (v0 - mu) * rstd * g[tid]       + b[tid];
    float o1 = (v1 - mu) * rstd * g[tid + 256] + b[tid + 256];
    if (y) {
        y[base + tid]       = o0;
        y[base + tid + 256] = o1;
    }
    if (yh) {
        __nv_bfloat16 h0, l0, h1, l1;
        split_bf16(o0, h0, l0);
        split_bf16(o1, h1, l1);
        yh[base + tid]       = h0;
        yh[base + tid + 256] = h1;
        yl[base + tid]       = l0;
        yl[base + tid + 256] = l1;
    }
}

// ---------------- mma attention, pre-split operands, cp.async pipelined -------
#define QT    64
#define KSPAN 320
#define SPAD  324
#define TSTR  72
#define TILE_B (64*TSTR*2)

#define A3_QH   0
#define A3_QL   9216
#define A3_K    18432
#define A3_V    55296
#define A3_S    92160
#define A3_LINV 175104
#define A3_BYTES 175360

__global__ void __launch_bounds__(256)
attn_kernel(const __nv_bfloat16* __restrict__ qh, const __nv_bfloat16* __restrict__ ql,
            const __nv_bfloat16* __restrict__ kh, const __nv_bfloat16* __restrict__ kl,
            const __nv_bfloat16* __restrict__ vth, const __nv_bfloat16* __restrict__ vtl,
            __nv_bfloat16* __restrict__ oh, __nv_bfloat16* __restrict__ ol)
{
    extern __shared__ char sm[];
    float* S    = (float*)(sm + A3_S);
    float* linv = (float*)(sm + A3_LINV);
    __nv_bfloat16* PH = (__nv_bfloat16*)(sm + A3_K);
    __nv_bfloat16* PL = (__nv_bfloat16*)(sm + A3_K + TILE_B);

    uint32_t uQH = smem_u32(sm) + A3_QH;
    uint32_t uQL = smem_u32(sm) + A3_QL;
    uint32_t uK  = smem_u32(sm) + A3_K;
    uint32_t uV  = smem_u32(sm) + A3_V;

    int tid  = threadIdx.x;
    int wid  = tid >> 5, lane = tid & 31;
    int mw   = (wid & 3) * 16;
    int nw   = (wid >> 2) * 32;

    int t0  = blockIdx.x * QT;
    int bh  = blockIdx.y;
    int b   = bh >> 3;
    int h   = bh & 7;
    int jbase = t0 - 256;

    int a_row  = mw + (lane & 15);
    int a_koff = (lane >> 4) * 8;
    int b_row  = nw + (lane & 7) + ((lane >> 4) & 1) * 8;
    int b_koff = ((lane >> 3) & 1) * 8;

    {
        #pragma unroll
        for (int it = 0; it < 4; it++) {
            int vi  = tid + 256 * it;
            int row = vi >> 4, c = vi & 15;
            const __nv_bfloat16* src = (c < 8 ? qh : ql)
                + (size_t)(b * SEQ + t0 + row) * DIM + h * DH + (c & 7) * 8;
            uint32_t dst = (c < 8 ? uQH : uQL) + row * (TSTR * 2) + (c & 7) * 16;
            cpa16(dst, src);
        }
    }

    auto load_k = [&](int s) {
        int kb = jbase + s * 64;
        uint32_t sb = uK + (s & 1) * (2 * TILE_B);
        #pragma unroll
        for (int it = 0; it < 4; it++) {
            int vi  = tid + 256 * it;
            int row = vi >> 4, c = vi & 15;
            int j = kb + row;
            int jc = j < 0 ? 0 : j;
            const __nv_bfloat16* src = (c < 8 ? kh : kl)
                + (size_t)(b * SEQ + jc) * DIM + h * DH + (c & 7) * 8;
            uint32_t dst = sb + (c < 8 ? 0 : TILE_B) + row * (TSTR * 2) + (c & 7) * 16;
            cpa16(dst, src);
        }
        asm volatile("cp.async.commit_group;" ::: "memory");
    };

    auto load_v = [&](int s) {
        int kb = jbase + s * 64;
        uint32_t sb = uV + (s & 1) * (2 * TILE_B);
        #pragma unroll
        for (int it = 0; it < 4; it++) {
            int vi  = tid + 256 * it;
            int row = vi >> 4, c = vi & 15;
            int j0 = kb + (c & 7) * 8;
            int jc = j0 < 0 ? 0 : j0;
            const __nv_bfloat16* src = (c < 8 ? vth : vtl)
                + (size_t)(b * DIM + h * DH + row) * SEQ + jc;
            uint32_t dst = sb + (c < 8 ? 0 : TILE_B) + row * (TSTR * 2) + (c & 7) * 16;
            cpa16(dst, src);
        }
        asm volatile("cp.async.commit_group;" ::: "memory");
    };

    // ---- phase 1: scores ----
    load_k(0);
    load_k(1);

    for (int s = 0; s < 5; s++) {
        if (s < 4) asm volatile("cp.async.wait_group 1;" ::: "memory");
        else       asm volatile("cp.async.wait_group 0;" ::: "memory");
        __syncthreads();

        uint32_t sKH = uK + (s & 1) * (2 * TILE_B);
        uint32_t sKL = sKH + TILE_B;
        int kb = jbase + s * 64;

        float acc[4][4];
        #pragma unroll
        for (int i = 0; i < 4; i++)
            #pragma unroll
            for (int j = 0; j < 4; j++) acc[i][j] = 0.f;

        #pragma unroll
        for (int k16 = 0; k16 < 4; k16++) {
            int kk0 = k16 * 16;
            uint32_t ah[4], al[4];
            uint32_t aoff = (a_row * TSTR + kk0 + a_koff) * 2;
            ldmx4(ah, uQH + aoff);
            ldmx4(al, uQL + aoff);
            #pragma unroll
            for (int ng = 0; ng < 2; ng++) {
                uint32_t bh2[4], bl2[4];
                uint32_t boff = ((b_row + ng * 16) * TSTR + kk0 + b_koff) * 2;
                ldmx4(bh2, sKH + boff);
                ldmx4(bl2, sKL + boff);
                mma_bf16(acc[2*ng],   ah, bh2);
                mma_bf16(acc[2*ng],   ah, bl2);
                mma_bf16(acc[2*ng],   al, bh2);
                mma_bf16(acc[2*ng+1], ah, bh2 + 2);
                mma_bf16(acc[2*ng+1], ah, bl2 + 2);
                mma_bf16(acc[2*ng+1], al, bh2 + 2);
            }
        }

        #pragma unroll
        for (int nt = 0; nt < 4; nt++) {
            #pragma unroll
            for (int half = 0; half < 2; half++) {
                int r = mw + (lane >> 2) + half * 8;
                int c = nw + nt * 8 + (lane & 3) * 2;
                int ig = t0 + r;
                #pragma unroll
                for (int e = 0; e < 2; e++) {
                    int jg = kb + c + e;
                    bool ok = (jg >= 0) && (jg <= ig) && (ig - jg < WIN);
                    S[r * SPAD + s * 64 + c + e] = ok ? acc[nt][half * 2 + e] : -INFINITY;
                }
            }
        }
        __syncthreads();
        if (s + 2 < 5) load_k(s + 2);
    }
    __syncthreads();

    // ---- phase 2: softmax ----
    {
        int r = tid >> 2, p = tid & 3;
        float m = -INFINITY;
        for (int cc = p; cc < KSPAN; cc += 4) m = fmaxf(m, S[r * SPAD + cc]);
        m = fmaxf(m, __shfl_xor_sync(0xffffffffu, m, 1));
        m = fmaxf(m, __shfl_xor_sync(0xffffffffu, m, 2));
        float sum = 0.f;
        for (int cc = p; cc < KSPAN; cc += 4) {
            float e = __expf(S[r * SPAD + cc] - m);
            S[r * SPAD + cc] = e;
            sum += e;
        }
        sum += __shfl_xor_sync(0xffffffffu, sum, 1);
        sum += __shfl_xor_sync(0xffffffffu, sum, 2);
        if (p == 0) linv[r] = 1.0f / sum;
    }
    __syncthreads();

    // ---- phase 3: O = P @ V ----
    load_v(0);
    load_v(1);

    float o[4][4];
    #pragma unroll
    for (int i = 0; i < 4; i++)
        #pragma unroll
        for (int j = 0; j < 4; j++) o[i][j] = 0.f;

    uint32_t uPH = uK, uPL = uK + TILE_B;

    for (int s = 0; s < 5; s++) {
        if (s < 4) asm volatile("cp.async.wait_group 1;" ::: "memory");
        else       asm volatile("cp.async.wait_group 0;" ::: "memory");
        __syncthreads();

        #pragma unroll
        for (int it = 0; it < 4; it++) {
            int vi  = tid + 256 * it;
            int row = vi >> 4, c4 = (vi & 15) * 4;
            float4 f = *reinterpret_cast<const float4*>(&S[row * SPAD + s * 64 + c4]);
            __nv_bfloat16 h0,l0,h1,l1,h2,l2,h3,l3;
            split_bf16(f.x, h0, l0); split_bf16(f.y, h1, l1);
            split_bf16(f.z, h2, l2); split_bf16(f.w, h3, l3);
            __nv_bfloat162 hh0; hh0.x=h0; hh0.y=h1;
            __nv_bfloat162 hh1; hh1.x=h2; hh1.y=h3;
            __nv_bfloat162 ll0; ll0.x=l0; ll0.y=l1;
            __nv_bfloat162 ll1; ll1.x=l2; ll1.y=l3;
            int oo = row * TSTR + c4;
            *reinterpret_cast<__nv_bfloat162*>(PH + oo)     = hh0;
            *reinterpret_cast<__nv_bfloat162*>(PH + oo + 2) = hh1;
            *reinterpret_cast<__nv_bfloat162*>(PL + oo)     = ll0;
            *reinterpret_cast<__nv_bfloat162*>(PL + oo + 2) = ll1;
        }
        __syncthreads();

        uint32_t sVH = uV + (s & 1) * (2 * TILE_B);
        uint32_t sVL = sVH + TILE_B;

        #pragma unroll
        for (int k16 = 0; k16 < 4; k16++) {
            int kk0 = k16 * 16;
            uint32_t ah[4], al[4];
            uint32_t aoff = (a_row * TSTR + kk0 + a_koff) * 2;
            ldmx4(ah, uPH + aoff);
            ldmx4(al, uPL + aoff);
            #pragma unroll
            for (int ng = 0; ng < 2; ng++) {
                uint32_t bh2[4], bl2[4];
                uint32_t boff = ((b_row + ng * 16) * TSTR + kk0 + b_koff) * 2;
                ldmx4(bh2, sVH + boff);
                ldmx4(bl2, sVL + boff);
                mma_bf16(o[2*ng],   ah, bh2);
                mma_bf16(o[2*ng],   ah, bl2);
                mma_bf16(o[2*ng],   al, bh2);
                mma_bf16(o[2*ng+1], ah, bh2 + 2);
                mma_bf16(o[2*ng+1], ah, bl2 + 2);
                mma_bf16(o[2*ng+1], al, bh2 + 2);
            }
        }
        __syncthreads();
        if (s + 2 < 5) load_v(s + 2);
    }

    #pragma unroll
    for (int nt = 0; nt < 4; nt++) {
        #pragma unroll
        for (int half = 0; half < 2; half++) {
            int r = mw + (lane >> 2) + half * 8;
            int d = nw + nt * 8 + (lane & 3) * 2;
            float li = linv[r];
            float v0 = o[nt][half * 2 + 0] * li;
            float v1 = o[nt][half * 2 + 1] * li;
            __nv_bfloat16 h0, l0, h1, l1;
            split_bf16(v0, h0, l0);
            split_bf16(v1, h1, l1);
            size_t base = (size_t)(b * SEQ + t0 + r) * DIM + h * DH + d;
            __nv_bfloat162 hh; hh.x = h0; hh.y = h1;
            __nv_bfloat162 ll; ll.x = l0; ll.y = l1;
            *reinterpret_cast<__nv_bfloat162*>(oh + base) = hh;
            *reinterpret_cast<__nv_bfloat162*>(ol + base) = ll;
        }
    }
}

// ---------------- host launcher ----------------------------------------------
extern "C" void kernel_launch(void* const* d_in, const int* in_sizes, int n_in,
                              void* d_out, int out_size)
{
    const float* tokens = (const float*)d_in[0];
    const float* Wq = (const float*)d_in[1];
    const float* Wk = (const float*)d_in[2];
    const float* Wv = (const float*)d_in[3];
    const float* Wo = (const float*)d_in[4];
    const float* bq = (const float*)d_in[5];
    const float* bk = (const float*)d_in[6];
    const float* bv = (const float*)d_in[7];
    const float* bo = (const float*)d_in[8];
    const float* W1 = (const float*)d_in[9];
    const float* b1 = (const float*)d_in[10];
    const float* W2 = (const float*)d_in[11];
    const float* b2 = (const float*)d_in[12];
    const float* g1 = (const float*)d_in[13];
    const float* be1= (const float*)d_in[14];
    const float* g2 = (const float*)d_in[15];
    const float* be2= (const float*)d_in[16];
    const float* gf = (const float*)d_in[17];
    const float* bf = (const float*)d_in[18];

    float *x, *q, *k, *v, *q2, *k2, *v2;
    cudaGetSymbolAddress((void**)&x,  g_x);
    cudaGetSymbolAddress((void**)&q,  g_q);
    cudaGetSymbolAddress((void**)&k,  g_k);
    cudaGetSymbolAddress((void**)&v,  g_v);
    cudaGetSymbolAddress((void**)&q2, g_q2);
    cudaGetSymbolAddress((void**)&k2, g_k2);
    cudaGetSymbolAddress((void**)&v2, g_v2);
    float* p0 = q;   // Wo/W2 partials reuse q/k (lifetimes disjoint)
    float* p1 = k;

    __nv_bfloat16 *xnh, *xnl, *atth, *attl, *hbh, *hbl;
    cudaGetSymbolAddress((void**)&xnh,  g_xnh);
    cudaGetSymbolAddress((void**)&xnl,  g_xnl);
    cudaGetSymbolAddress((void**)&atth, g_atth);
    cudaGetSymbolAddress((void**)&attl, g_attl);
    cudaGetSymbolAddress((void**)&hbh,  g_hbh);
    cudaGetSymbolAddress((void**)&hbl,  g_hbl);

    __nv_bfloat16 *qh, *ql, *kh, *kl, *vth, *vtl;
    cudaGetSymbolAddress((void**)&qh,  g_qh);
    cudaGetSymbolAddress((void**)&ql,  g_ql);
    cudaGetSymbolAddress((void**)&kh,  g_kh);
    cudaGetSymbolAddress((void**)&kl,  g_kl);
    cudaGetSymbolAddress((void**)&vth, g_vth);
    cudaGetSymbolAddress((void**)&vtl, g_vtl);

    __nv_bfloat16 *wqh,*wql,*wkh,*wkl,*wvh,*wvl,*woh,*wol,*w1h,*w1l,*w2h,*w2l;
    cudaGetSymbolAddress((void**)&wqh, g_wqt_h); cudaGetSymbolAddress((void**)&wql, g_wqt_l);
    cudaGetSymbolAddress((void**)&wkh, g_wkt_h); cudaGetSymbolAddress((void**)&wkl, g_wkt_l);
    cudaGetSymbolAddress((void**)&wvh, g_wvt_h); cudaGetSymbolAddress((void**)&wvl, g_wvt_l);
    cudaGetSymbolAddress((void**)&woh, g_wot_h); cudaGetSymbolAddress((void**)&wol, g_wot_l);
    cudaGetSymbolAddress((void**)&w1h, g_w1t_h); cudaGetSymbolAddress((void**)&w1l, g_w1t_l);
    cudaGetSymbolAddress((void**)&w2h, g_w2t_h); cudaGetSymbolAddress((void**)&w2l, g_w2t_l);

    cudaFuncSetAttribute(attn_kernel, cudaFuncAttributeMaxDynamicSharedMemorySize,
                         A3_BYTES);
    cudaFuncSetAttribute(qkv_mm, cudaFuncAttributeMaxDynamicSharedMemorySize, DSM_BYTES);
    cudaFuncSetAttribute(gemm_ksplit, cudaFuncAttributeMaxDynamicSharedMemorySize, DSM_BYTES);
    cudaFuncSetAttribute(gemm_mm<1,0,0,1>, cudaFuncAttributeMaxDynamicSharedMemorySize, DSM_BYTES);

    cudaMemcpyAsync(x, tokens, sizeof(float) * (size_t)BT * DIM,
                    cudaMemcpyDeviceToDevice, 0);

    // weight conversion
    {
        dim3 blk(32, 8);
        dim3 gdd(DIM / 32, DIM / 32, NL);
        wconv_kernel<<<gdd, blk>>>(Wq, wqh, wql, DIM, DIM);
        wconv_kernel<<<gdd, blk>>>(Wk, wkh, wkl, DIM, DIM);
        wconv_kernel<<<gdd, blk>>>(Wv, wvh, wvl, DIM, DIM);
        wconv_kernel<<<gdd, blk>>>(Wo, woh, wol, DIM, DIM);
        dim3 g1d(DFF / 32, DIM / 32, NL);
        wconv_kernel<<<g1d, blk>>>(W1, w1h, w1l, DIM, DFF);
        dim3 g2d(DIM / 32, DFF / 32, NL);
        wconv_kernel<<<g2d, blk>>>(W2, w2h, w2l, DFF, DIM);
    }

    dim3 gQKV(DIM / 128, BT / 128, 6);   // 3 outputs x 2 k-halves = 768 CTAs
    dim3 gKS (DIM / 128, BT / 128, 2);   // split-K=2 for Wo/W2
    dim3 gF  (DFF / 128, BT / 128);
    dim3 gAtt(SEQ / QT, BATCH * NH);
    dim3 gVc (SEQ / 32, DIM / 32, BATCH);

    for (int l = 0; l < NL; l++) {
        size_t wofs  = (size_t)l * DIM * DIM;
        size_t w1ofs = (size_t)l * DIM * DFF;

        // ln1: fold previous layer's W2 partials (layers >= 1)
        const float* pp0 = (l == 0) ? nullptr : p0;
        const float* pp1 = (l == 0) ? nullptr : p1;
        float* xo = (l == 0) ? nullptr : x;
        ln_kernel<<<BT, 256>>>(x, pp0, pp1, g1 + l * DIM, be1 + l * DIM,
                               xo, nullptr, xnh, xnl);

        qkv_mm<<<gQKV, 256, DSM_BYTES>>>(xnh, xnl,
                                         wqh + wofs, wql + wofs,
                                         wkh + wofs, wkl + wofs,
                                         wvh + wofs, wvl + wofs,
                                         bq + l * DIM, bk + l * DIM, bv + l * DIM,
                                         q, q2, k, k2, v, v2);

        ropesplit_kernel<<<(BT * NH * 32) / 256, 256>>>(q, q2, k, k2, qh, ql, kh, kl);
        vconv_kernel<<<gVc, dim3(32, 8)>>>(v, v2, vth, vtl);

        attn_kernel<<<gAtt, 256, A3_BYTES>>>(qh, ql, kh, kl, vth, vtl, atth, attl);

        // Wo split-K=2 -> partials p0,p1 (q/k buffers now free)
        gemm_ksplit<<<gKS, 256, DSM_BYTES>>>(atth, attl, woh + wofs, wol + wofs,
                                             bo + l * DIM, p0, p1, DIM, DIM);

        // ln2: x = x + p0 + p1 (write back), then LN
        ln_kernel<<<BT, 256>>>(x, p0, p1, g2 + l * DIM, be2 + l * DIM,
                               x, nullptr, xnh, xnl);

        gemm_mm<1,0,0,1><<<gF, 256, DSM_BYTES>>>(xnh, xnl, w1h + w1ofs, w1l + w1ofs,
                                                 b1 + l * DFF, nullptr, nullptr, hbh, hbl,
                                                 DFF, DIM);

        // W2 split-K=2 -> partials p0,p1 (folded by next ln1 / final ln)
        gemm_ksplit<<<gKS, 256, DSM_BYTES>>>(hbh, hbl, w2h + w1ofs, w2l + w1ofs,
                                             b2 + l * DIM, p0, p1, DIM, DFF);
    }

    // final LN folds last W2 partials
    ln_kernel<<<BT, 256>>>(x, p0, p1, gf, bf, nullptr, (float*)d_out,
                           nullptr, nullptr);
}

// round 14
// speedup vs baseline: 1.0149x; 1.0149x over previous
#include <cuda_runtime.h>
#include <cuda_bf16.h>
#include <math.h>
#include <stdint.h>

#define BATCH 2
#define SEQ   2048
#define DIM   512
#define NH    8
#define DH    64
#define NL    4
#define DFF   2048
#define WIN   256
#define BT    (BATCH*SEQ)   // 4096

// ---------------- scratch (static device globals; no allocation) -------------
__device__ float g_x [BT*DIM];
__device__ float g_q [BT*DIM];    // q ; later Wo/W2 split-K partial 0
__device__ float g_k [BT*DIM];    // k ; later Wo/W2 split-K partial 1
__device__ float g_v [BT*DIM];

__device__ __nv_bfloat16 g_xnh [BT*DIM];
__device__ __nv_bfloat16 g_xnl [BT*DIM];
__device__ __nv_bfloat16 g_atth[BT*DIM];
__device__ __nv_bfloat16 g_attl[BT*DIM];
__device__ __nv_bfloat16 g_hbh [BT*DFF];
__device__ __nv_bfloat16 g_hbl [BT*DFF];

// attention operands (pre-split)
__device__ __nv_bfloat16 g_qh [BT*DIM], g_ql [BT*DIM];
__device__ __nv_bfloat16 g_kh [BT*DIM], g_kl [BT*DIM];
__device__ __nv_bfloat16 g_vth[BT*DIM], g_vtl[BT*DIM];   // [b*512+d][SEQ]

// transposed split weights: [L][N][K]
__device__ __nv_bfloat16 g_wqt_h[NL*DIM*DIM],  g_wqt_l[NL*DIM*DIM];
__device__ __nv_bfloat16 g_wkt_h[NL*DIM*DIM],  g_wkt_l[NL*DIM*DIM];
__device__ __nv_bfloat16 g_wvt_h[NL*DIM*DIM],  g_wvt_l[NL*DIM*DIM];
__device__ __nv_bfloat16 g_wot_h[NL*DIM*DIM],  g_wot_l[NL*DIM*DIM];
__device__ __nv_bfloat16 g_w1t_h[NL*DIM*DFF],  g_w1t_l[NL*DIM*DFF];
__device__ __nv_bfloat16 g_w2t_h[NL*DFF*DIM],  g_w2t_l[NL*DFF*DIM];

// ---------------- PTX helpers --------------------------------------------------
__device__ __forceinline__ uint32_t smem_u32(const void* p) {
    uint32_t a;
    asm("{ .reg .u64 t; cvta.to.shared.u64 t, %1; cvt.u32.u64 %0, t; }"
        : "=r"(a) : "l"(p));
    return a;
}

__device__ __forceinline__ void cpa16(uint32_t dst, const void* src)
{
    asm volatile("cp.async.cg.shared.global [%0], [%1], 16;" :: "r"(dst), "l"(src));
}

__device__ __forceinline__ void ldmx4(uint32_t* r, uint32_t addr)
{
    asm volatile("ldmatrix.sync.aligned.m8n8.x4.shared.b16 {%0,%1,%2,%3}, [%4];"
        : "=r"(r[0]), "=r"(r[1]), "=r"(r[2]), "=r"(r[3]) : "r"(addr));
}

__device__ __forceinline__ void mma_bf16(float* c, const uint32_t* a, const uint32_t* b)
{
    asm volatile(
        "mma.sync.aligned.m16n8k16.row.col.f32.bf16.bf16.f32 "
        "{%0,%1,%2,%3}, {%4,%5,%6,%7}, {%8,%9}, {%0,%1,%2,%3};"
        : "+f"(c[0]), "+f"(c[1]), "+f"(c[2]), "+f"(c[3])
        : "r"(a[0]), "r"(a[1]), "r"(a[2]), "r"(a[3]), "r"(b[0]), "r"(b[1]));
}

__device__ __forceinline__ void split_bf16(float v, __nv_bfloat16& h, __nv_bfloat16& l)
{
    h = __float2bfloat16(v);
    l = __float2bfloat16(v - __bfloat162float(h));
}

// ---------------- mma.sync bf16-split GEMM (2-stage, 2 CTAs/SM) ----------------
#define TKC       32
#define RSTR      40
#define ARR_BYTES (128*RSTR*2)
#define STG_BYTES (4*ARR_BYTES)       // 40960
#define DSM_BYTES (2*STG_BYTES)       // 81920 -> 2 CTAs/SM

template <int GELU, int RES, int OUTF32, int OUTBF>
__device__ __forceinline__ void gemm_mm_core(
    const __nv_bfloat16* __restrict__ Ah, const __nv_bfloat16* __restrict__ Al,
    const __nv_bfloat16* __restrict__ Bh, const __nv_bfloat16* __restrict__ Bl,
    const float* __restrict__ bias, const float* __restrict__ res,
    float* __restrict__ C, __nv_bfloat16* __restrict__ Oh, __nv_bfloat16* __restrict__ Ol,
    int N, int Kstr, int kbase, int Kloop, int m0, int n0)
{
    extern __shared__ char dsm[];
    uint32_t sm0 = smem_u32(dsm);

    int tid  = threadIdx.x;
    int wid  = tid >> 5, lane = tid & 31;
    int mw   = (wid & 3) * 32;
    int nw   = (wid >> 2) * 64;

    float acc[2][8][4];
    #pragma unroll
    for (int i = 0; i < 2; i++)
        #pragma unroll
        for (int j = 0; j < 8; j++)
            #pragma unroll
            for (int t = 0; t < 4; t++) acc[i][j][t] = 0.f;

    int nk = Kloop / TKC;

    auto load_stage = [&](int c) {
        uint32_t sb = sm0 + (c & 1) * STG_BYTES;
        int k0 = kbase + c * TKC;
        #pragma unroll
        for (int it = 0; it < 8; it++) {
            int idx  = it * 256 + tid;
            int arr  = idx >> 9;
            int rem  = idx & 511;
            int row  = rem >> 2;
            int part = rem & 3;
            uint32_t dst = sb + arr * ARR_BYTES + row * (RSTR * 2) + part * 16;
            const __nv_bfloat16* src;
            if      (arr == 0) src = Ah + (size_t)(m0 + row) * Kstr + k0 + part * 8;
            else if (arr == 1) src = Al + (size_t)(m0 + row) * Kstr + k0 + part * 8;
            else if (arr == 2) src = Bh + (size_t)(n0 + row) * Kstr + k0 + part * 8;
            else               src = Bl + (size_t)(n0 + row) * Kstr + k0 + part * 8;
            cpa16(dst, src);
        }
        asm volatile("cp.async.commit_group;" ::: "memory");
    };

    load_stage(0);

    int a_row = mw + (lane & 15);
    int a_koff = (lane >> 4) * 8;
    int b_row = nw + (lane & 7) + ((lane >> 4) & 1) * 8;
    int b_koff = ((lane >> 3) & 1) * 8;

    for (int c = 0; c < nk; c++) {
        asm volatile("cp.async.wait_group 0;" ::: "memory");
        __syncthreads();

        if (c + 1 < nk) load_stage(c + 1);

        uint32_t sb  = sm0 + (c & 1) * STG_BYTES;
        uint32_t sah = sb;
        uint32_t sal = sb + ARR_BYTES;
        uint32_t sbh = sb + 2 * ARR_BYTES;
        uint32_t sbl = sb + 3 * ARR_BYTES;

        #pragma unroll
        for (int h = 0; h < 2; h++) {
            int k0 = h * 16;
            uint32_t ah[2][4], al[2][4];
            #pragma unroll
            for (int mt = 0; mt < 2; mt++) {
                uint32_t off = ((a_row + mt * 16) * RSTR + k0 + a_koff) * 2;
                ldmx4(ah[mt], sah + off);
                ldmx4(al[mt], sal + off);
            }
            #pragma unroll
            for (int ng = 0; ng < 4; ng++) {
                uint32_t bh[4], bl[4];
                uint32_t off = ((b_row + ng * 16) * RSTR + k0 + b_koff) * 2;
                ldmx4(bh, sbh + off);
                ldmx4(bl, sbl + off);
                #pragma unroll
                for (int mt = 0; mt < 2; mt++) {
                    mma_bf16(acc[mt][2*ng],   ah[mt], bh);
                    mma_bf16(acc[mt][2*ng],   ah[mt], bl);
                    mma_bf16(acc[mt][2*ng],   al[mt], bh);
                    mma_bf16(acc[mt][2*ng+1], ah[mt], bh + 2);
                    mma_bf16(acc[mt][2*ng+1], ah[mt], bl + 2);
                    mma_bf16(acc[mt][2*ng+1], al[mt], bh + 2);
                }
            }
        }
        __syncthreads();
    }

    int cbase_n = n0 + nw + (lane & 3) * 2;
    #pragma unroll
    for (int mt = 0; mt < 2; mt++) {
        #pragma unroll
        for (int half = 0; half < 2; half++) {
            int row = m0 + mw + mt * 16 + (lane >> 2) + half * 8;
            size_t rbase = (size_t)row * N;
            #pragma unroll
            for (int nt = 0; nt < 8; nt++) {
                int col = cbase_n + nt * 8;
                float v0 = acc[mt][nt][half * 2 + 0];
                float v1 = acc[mt][nt][half * 2 + 1];
                if (bias) {
                    float2 b2 = *reinterpret_cast<const float2*>(bias + col);
                    v0 += b2.x; v1 += b2.y;
                }
                if (GELU) {
                    v0 = 0.5f * v0 * (1.0f + erff(v0 * 0.70710678118654752f));
                    v1 = 0.5f * v1 * (1.0f + erff(v1 * 0.70710678118654752f));
                }
                if (RES) {
                    float2 r2 = *reinterpret_cast<const float2*>(res + rbase + col);
                    v0 += r2.x; v1 += r2.y;
                }
                if (OUTF32) {
                    *reinterpret_cast<float2*>(C + rbase + col) = make_float2(v0, v1);
                }
                if (OUTBF) {
                    __nv_bfloat16 h0, l0, h1, l1;
                    split_bf16(v0, h0, l0);
                    split_bf16(v1, h1, l1);
                    __nv_bfloat162 hh; hh.x = h0; hh.y = h1;
                    __nv_bfloat162 ll; ll.x = l0; ll.y = l1;
                    *reinterpret_cast<__nv_bfloat162*>(Oh + rbase + col) = hh;
                    *reinterpret_cast<__nv_bfloat162*>(Ol + rbase + col) = ll;
                }
            }
        }
    }
}

// plain GEMM (full K)
template <int GELU, int RES, int OUTF32, int OUTBF>
__global__ void __launch_bounds__(256, 2)
gemm_mm(const __nv_bfloat16* __restrict__ Ah, const __nv_bfloat16* __restrict__ Al,
        const __nv_bfloat16* __restrict__ Bh, const __nv_bfloat16* __restrict__ Bl,
        const float* __restrict__ bias, const float* __restrict__ res,
        float* __restrict__ C, __nv_bfloat16* __restrict__ Oh,
        __nv_bfloat16* __restrict__ Ol, int N, int K)
{
    gemm_mm_core<GELU, RES, OUTF32, OUTBF>(Ah, Al, Bh, Bl, bias, res, C, Oh, Ol,
                                           N, K, 0, K, blockIdx.y * 128, blockIdx.x * 128);
}

// split-K=2 GEMM: grid.z selects k-half; writes fp32 partial (bias only in half 0)
__global__ void __launch_bounds__(256, 2)
gemm_ksplit(const __nv_bfloat16* __restrict__ Ah, const __nv_bfloat16* __restrict__ Al,
            const __nv_bfloat16* __restrict__ Bh, const __nv_bfloat16* __restrict__ Bl,
            const float* __restrict__ bias,
            float* __restrict__ p0, float* __restrict__ p1, int N, int K)
{
    int kz = blockIdx.z;
    float* C = kz ? p1 : p0;
    const float* bi = kz ? nullptr : bias;
    gemm_mm_core<0, 0, 1, 0>(Ah, Al, Bh, Bl, bi, nullptr, C, nullptr, nullptr,
                             N, K, kz * (K / 2), K / 2,
                             blockIdx.y * 128, blockIdx.x * 128);
}

// fused QKV (full K): grid.z selects output
__global__ void __launch_bounds__(256, 2)
qkv_mm(const __nv_bfloat16* __restrict__ Ah, const __nv_bfloat16* __restrict__ Al,
       const __nv_bfloat16* __restrict__ Bqh, const __nv_bfloat16* __restrict__ Bql,
       const __nv_bfloat16* __restrict__ Bkh, const __nv_bfloat16* __restrict__ Bkl,
       const __nv_bfloat16* __restrict__ Bvh, const __nv_bfloat16* __restrict__ Bvl,
       const float* __restrict__ bq, const float* __restrict__ bk,
       const float* __restrict__ bv,
       float* __restrict__ q, float* __restrict__ k, float* __restrict__ v)
{
    int z = blockIdx.z;
    const __nv_bfloat16* Bh = (z == 0) ? Bqh : (z == 1) ? Bkh : Bvh;
    const __nv_bfloat16* Bl = (z == 0) ? Bql : (z == 1) ? Bkl : Bvl;
    const float* bi = (z == 0) ? bq : (z == 1) ? bk : bv;
    float* C        = (z == 0) ? q  : (z == 1) ? k  : v;
    gemm_mm_core<0, 0, 1, 0>(Ah, Al, Bh, Bl, bi, nullptr, C, nullptr, nullptr,
                             DIM, DIM, 0, DIM, blockIdx.y * 128, blockIdx.x * 128);
}

// ---------------- weight transpose + bf16 split -------------------------------
__global__ void wconv_kernel(const float* __restrict__ W,
                             __nv_bfloat16* __restrict__ hiT,
                             __nv_bfloat16* __restrict__ loT, int K, int N)
{
    __shared__ float t[32][33];
    int n0 = blockIdx.x * 32, k0 = blockIdx.y * 32;
    size_t lofs = (size_t)blockIdx.z * K * N;
    const float* Wl = W + lofs;
    int tx = threadIdx.x, ty = threadIdx.y;
    #pragma unroll
    for (int i = 0; i < 4; i++)
        t[ty + 8 * i][tx] = Wl[(size_t)(k0 + ty + 8 * i) * N + n0 + tx];
    __syncthreads();
    __nv_bfloat16* ho = hiT + lofs;
    __nv_bfloat16* lo = loT + lofs;
    #pragma unroll
    for (int i = 0; i < 4; i++) {
        float v = t[tx][ty + 8 * i];
        __nv_bfloat16 h, l;
        split_bf16(v, h, l);
        ho[(size_t)(n0 + ty + 8 * i) * K + k0 + tx] = h;
        lo[(size_t)(n0 + ty + 8 * i) * K + k0 + tx] = l;
    }
}

// ---------------- combined qkv prep: RoPE-split (q,k) + V transpose-split ------
// blocks [0, 4096): ropesplit over BT*NH*32 = 1048576 elements (256 thr each)
// blocks [4096, 6144): vconv tiles; vb = bid-4096: t0=(vb&63)*32, d0=((vb>>6)&15)*32, b=vb>>10
#define PREP_ROPE_BLOCKS ((BT*NH*32)/256)            // 4096
#define PREP_V_BLOCKS    ((SEQ/32)*(DIM/32)*BATCH)   // 2048
#define PREP_BLOCKS      (PREP_ROPE_BLOCKS + PREP_V_BLOCKS)

__global__ void __launch_bounds__(256)
qkvprep_kernel(const float* __restrict__ q, const float* __restrict__ k,
               const float* __restrict__ v,
               __nv_bfloat16* __restrict__ qh, __nv_bfloat16* __restrict__ ql,
               __nv_bfloat16* __restrict__ kh, __nv_bfloat16* __restrict__ kl,
               __nv_bfloat16* __restrict__ vth, __nv_bfloat16* __restrict__ vtl)
{
    int bid = blockIdx.x;
    int tid = threadIdx.x;

    if (bid < PREP_ROPE_BLOCKS) {
        int idx = bid * 256 + tid;          // over BT*NH*32
        int d  = idx & 31;
        int h  = (idx >> 5) & (NH - 1);
        int bt = idx >> 8;
        int t  = bt & (SEQ - 1);

        float inv_freq = __powf(10000.0f, -(float)(2 * d) / (float)DH);
        float ang = (float)t * inv_freq;
        float c, s;
        sincosf(ang, &s, &c);

        size_t base = (size_t)bt * DIM + h * DH + d;

        float q1 = q[base], q2 = q[base + 32];
        float qo1 = (q1 * c - q2 * s) * 0.125f;
        float qo2 = (q2 * c + q1 * s) * 0.125f;
        __nv_bfloat16 hh, ll;
        split_bf16(qo1, hh, ll); qh[base] = hh;      ql[base] = ll;
        split_bf16(qo2, hh, ll); qh[base + 32] = hh; ql[base + 32] = ll;

        float k1 = k[base], k2 = k[base + 32];
        float ko1 = k1 * c - k2 * s;
        float ko2 = k2 * c + k1 * s;
        split_bf16(ko1, hh, ll); kh[base] = hh;      kl[base] = ll;
        split_bf16(ko2, hh, ll); kh[base + 32] = hh; kl[base + 32] = ll;
    } else {
        __shared__ float t[32][33];
        int vb = bid - PREP_ROPE_BLOCKS;
        int t0 = (vb & 63) * 32;
        int d0 = ((vb >> 6) & 15) * 32;
        int b  = vb >> 10;
        int tx = tid & 31, ty = tid >> 5;
        #pragma unroll
        for (int i = 0; i < 4; i++)
            t[ty + 8 * i][tx] = v[(size_t)(b * SEQ + t0 + ty + 8 * i) * DIM + d0 + tx];
        __syncthreads();
        #pragma unroll
        for (int i = 0; i < 4; i++) {
            float val = t[tx][ty + 8 * i];
            __nv_bfloat16 h, l;
            split_bf16(val, h, l);
            size_t o = (size_t)(b * DIM + d0 + ty + 8 * i) * SEQ + t0 + tx;
            vth[o] = h;
            vtl[o] = l;
        }
    }
}

// ---------------- LayerNorm (optionally folds split-K partials) ----------------
__global__ void ln_kernel(const float* __restrict__ x,
                          const float* __restrict__ p0, const float* __restrict__ p1,
                          const float* __restrict__ g, const float* __restrict__ b,
                          float* __restrict__ xout, float* __restrict__ y,
                          __nv_bfloat16* __restrict__ yh, __nv_bfloat16* __restrict__ yl)
{
    int row = blockIdx.x;
    int tid = threadIdx.x;
    size_t base = (size_t)row * DIM;

    float v0 = x[base + tid];
    float v1 = x[base + tid + 256];
    if (p0) {
        v0 += p0[base + tid] + p1[base + tid];
        v1 += p0[base + tid + 256] + p1[base + tid + 256];
    }
    if (xout) {
        xout[base + tid]       = v0;
        xout[base + tid + 256] = v1;
    }

    float s  = v0 + v1;
    float ss = v0 * v0 + v1 * v1;
    #pragma unroll
    for (int o = 16; o; o >>= 1) {
        s  += __shfl_xor_sync(0xffffffffu, s,  o);
        ss += __shfl_xor_sync(0xffffffffu, ss, o);
    }
    __shared__ float ws[8], wss[8];
    int w = tid >> 5, ln = tid & 31;
    if (ln == 0) { ws[w] = s; wss[w] = ss; }
    __syncthreads();
    __shared__ float s_mu, s_rstd;
    if (tid == 0) {
        float S = 0.f, SS = 0.f;
        #pragma unroll
        for (int i = 0; i < 8; i++) { S += ws[i]; SS += wss[i]; }
        float mu  = S * (1.0f / DIM);
        float var = SS * (1.0f / DIM) - mu * mu;
        s_mu = mu; s_rstd = rsqrtf(var + 1e-5f);
    }
    __syncthreads();
    float mu = s_mu, rstd = s_rstd;
    float o0 = (v0 - mu) * rstd * g[tid]       + b[tid];
    float o1 = (v1 - mu) * rstd * g[tid + 256] + b[tid + 256];
    if (y) {
        y[base + tid]       = o0;
        y[base + tid + 256] = o1;
    }
    if (yh) {
        __nv_bfloat16 h0, l0, h1, l1;
        split_bf16(o0, h0, l0);
        split_bf16(o1, h1, l1);
        yh[base + tid]       = h0;
        yh[base + tid + 256] = h1;
        yl[base + tid]       = l0;
        yl[base + tid + 256] = l1;
    }
}

// ---------------- mma attention, pre-split operands, cp.async pipelined -------
#define QT    64
#define KSPAN 320
#define SPAD  324
#define TSTR  72
#define TILE_B (64*TSTR*2)

#define A3_QH   0
#define A3_QL   9216
#define A3_K    18432
#define A3_V    55296
#define A3_S    92160
#define A3_LINV 175104
#define A3_BYTES 175360

__global__ void __launch_bounds__(256)
attn_kernel(const __nv_bfloat16* __restrict__ qh, const __nv_bfloat16* __restrict__ ql,
            const __nv_bfloat16* __restrict__ kh, const __nv_bfloat16* __restrict__ kl,
            const __nv_bfloat16* __restrict__ vth, const __nv_bfloat16* __restrict__ vtl,
            __nv_bfloat16* __restrict__ oh, __nv_bfloat16* __restrict__ ol)
{
    extern __shared__ char sm[];
    float* S    = (float*)(sm + A3_S);
    float* linv = (float*)(sm + A3_LINV);
    __nv_bfloat16* PH = (__nv_bfloat16*)(sm + A3_K);
    __nv_bfloat16* PL = (__nv_bfloat16*)(sm + A3_K + TILE_B);

    uint32_t uQH = smem_u32(sm) + A3_QH;
    uint32_t uQL = smem_u32(sm) + A3_QL;
    uint32_t uK  = smem_u32(sm) + A3_K;
    uint32_t uV  = smem_u32(sm) + A3_V;

    int tid  = threadIdx.x;
    int wid  = tid >> 5, lane = tid & 31;
    int mw   = (wid & 3) * 16;
    int nw   = (wid >> 2) * 32;

    int t0  = blockIdx.x * QT;
    int bh  = blockIdx.y;
    int b   = bh >> 3;
    int h   = bh & 7;
    int jbase = t0 - 256;

    int a_row  = mw + (lane & 15);
    int a_koff = (lane >> 4) * 8;
    int b_row  = nw + (lane & 7) + ((lane >> 4) & 1) * 8;
    int b_koff = ((lane >> 3) & 1) * 8;

    {
        #pragma unroll
        for (int it = 0; it < 4; it++) {
            int vi  = tid + 256 * it;
            int row = vi >> 4, c = vi & 15;
            const __nv_bfloat16* src = (c < 8 ? qh : ql)
                + (size_t)(b * SEQ + t0 + row) * DIM + h * DH + (c & 7) * 8;
            uint32_t dst = (c < 8 ? uQH : uQL) + row * (TSTR * 2) + (c & 7) * 16;
            cpa16(dst, src);
        }
    }

    auto load_k = [&](int s) {
        int kb = jbase + s * 64;
        uint32_t sb = uK + (s & 1) * (2 * TILE_B);
        #pragma unroll
        for (int it = 0; it < 4; it++) {
            int vi  = tid + 256 * it;
            int row = vi >> 4, c = vi & 15;
            int j = kb + row;
            int jc = j < 0 ? 0 : j;
            const __nv_bfloat16* src = (c < 8 ? kh : kl)
                + (size_t)(b * SEQ + jc) * DIM + h * DH + (c & 7) * 8;
            uint32_t dst = sb + (c < 8 ? 0 : TILE_B) + row * (TSTR * 2) + (c & 7) * 16;
            cpa16(dst, src);
        }
        asm volatile("cp.async.commit_group;" ::: "memory");
    };

    auto load_v = [&](int s) {
        int kb = jbase + s * 64;
        uint32_t sb = uV + (s & 1) * (2 * TILE_B);
        #pragma unroll
        for (int it = 0; it < 4; it++) {
            int vi  = tid + 256 * it;
            int row = vi >> 4, c = vi & 15;
            int j0 = kb + (c & 7) * 8;
            int jc = j0 < 0 ? 0 : j0;
            const __nv_bfloat16* src = (c < 8 ? vth : vtl)
                + (size_t)(b * DIM + h * DH + row) * SEQ + jc;
            uint32_t dst = sb + (c < 8 ? 0 : TILE_B) + row * (TSTR * 2) + (c & 7) * 16;
            cpa16(dst, src);
        }
        asm volatile("cp.async.commit_group;" ::: "memory");
    };

    // ---- phase 1: scores ----
    load_k(0);
    load_k(1);

    for (int s = 0; s < 5; s++) {
        if (s < 4) asm volatile("cp.async.wait_group 1;" ::: "memory");
        else       asm volatile("cp.async.wait_group 0;" ::: "memory");
        __syncthreads();

        uint32_t sKH = uK + (s & 1) * (2 * TILE_B);
        uint32_t sKL = sKH + TILE_B;
        int kb = jbase + s * 64;

        float acc[4][4];
        #pragma unroll
        for (int i = 0; i < 4; i++)
            #pragma unroll
            for (int j = 0; j < 4; j++) acc[i][j] = 0.f;

        #pragma unroll
        for (int k16 = 0; k16 < 4; k16++) {
            int kk0 = k16 * 16;
            uint32_t ah[4], al[4];
            uint32_t aoff = (a_row * TSTR + kk0 + a_koff) * 2;
            ldmx4(ah, uQH + aoff);
            ldmx4(al, uQL + aoff);
            #pragma unroll
            for (int ng = 0; ng < 2; ng++) {
                uint32_t bh2[4], bl2[4];
                uint32_t boff = ((b_row + ng * 16) * TSTR + kk0 + b_koff) * 2;
                ldmx4(bh2, sKH + boff);
                ldmx4(bl2, sKL + boff);
                mma_bf16(acc[2*ng],   ah, bh2);
                mma_bf16(acc[2*ng],   ah, bl2);
                mma_bf16(acc[2*ng],   al, bh2);
                mma_bf16(acc[2*ng+1], ah, bh2 + 2);
                mma_bf16(acc[2*ng+1], ah, bl2 + 2);
                mma_bf16(acc[2*ng+1], al, bh2 + 2);
            }
        }

        #pragma unroll
        for (int nt = 0; nt < 4; nt++) {
            #pragma unroll
            for (int half = 0; half < 2; half++) {
                int r = mw + (lane >> 2) + half * 8;
                int c = nw + nt * 8 + (lane & 3) * 2;
                int ig = t0 + r;
                #pragma unroll
                for (int e = 0; e < 2; e++) {
                    int jg = kb + c + e;
                    bool ok = (jg >= 0) && (jg <= ig) && (ig - jg < WIN);
                    S[r * SPAD + s * 64 + c + e] = ok ? acc[nt][half * 2 + e] : -INFINITY;
                }
            }
        }
        __syncthreads();
        if (s + 2 < 5) load_k(s + 2);
    }
    __syncthreads();

    // ---- phase 2: softmax ----
    {
        int r = tid >> 2, p = tid & 3;
        float m = -INFINITY;
        for (int cc = p; cc < KSPAN; cc += 4) m = fmaxf(m, S[r * SPAD + cc]);
        m = fmaxf(m, __shfl_xor_sync(0xffffffffu, m, 1));
        m = fmaxf(m, __shfl_xor_sync(0xffffffffu, m, 2));
        float sum = 0.f;
        for (int cc = p; cc < KSPAN; cc += 4) {
            float e = __expf(S[r * SPAD + cc] - m);
            S[r * SPAD + cc] = e;
            sum += e;
        }
        sum += __shfl_xor_sync(0xffffffffu, sum, 1);
        sum += __shfl_xor_sync(0xffffffffu, sum, 2);
        if (p == 0) linv[r] = 1.0f / sum;
    }
    __syncthreads();

    // ---- phase 3: O = P @ V ----
    load_v(0);
    load_v(1);

    float o[4][4];
    #pragma unroll
    for (int i = 0; i < 4; i++)
        #pragma unroll
        for (int j = 0; j < 4; j++) o[i][j] = 0.f;

    uint32_t uPH = uK, uPL = uK + TILE_B;

    for (int s = 0; s < 5; s++) {
        if (s < 4) asm volatile("cp.async.wait_group 1;" ::: "memory");
        else       asm volatile("cp.async.wait_group 0;" ::: "memory");
        __syncthreads();

        #pragma unroll
        for (int it = 0; it < 4; it++) {
            int vi  = tid + 256 * it;
            int row = vi >> 4, c4 = (vi & 15) * 4;
            float4 f = *reinterpret_cast<const float4*>(&S[row * SPAD + s * 64 + c4]);
            __nv_bfloat16 h0,l0,h1,l1,h2,l2,h3,l3;
            split_bf16(f.x, h0, l0); split_bf16(f.y, h1, l1);
            split_bf16(f.z, h2, l2); split_bf16(f.w, h3, l3);
            __nv_bfloat162 hh0; hh0.x=h0; hh0.y=h1;
            __nv_bfloat162 hh1; hh1.x=h2; hh1.y=h3;
            __nv_bfloat162 ll0; ll0.x=l0; ll0.y=l1;
            __nv_bfloat162 ll1; ll1.x=l2; ll1.y=l3;
            int oo = row * TSTR + c4;
            *reinterpret_cast<__nv_bfloat162*>(PH + oo)     = hh0;
            *reinterpret_cast<__nv_bfloat162*>(PH + oo + 2) = hh1;
            *reinterpret_cast<__nv_bfloat162*>(PL + oo)     = ll0;
            *reinterpret_cast<__nv_bfloat162*>(PL + oo + 2) = ll1;
        }
        __syncthreads();

        uint32_t sVH = uV + (s & 1) * (2 * TILE_B);
        uint32_t sVL = sVH + TILE_B;

        #pragma unroll
        for (int k16 = 0; k16 < 4; k16++) {
            int kk0 = k16 * 16;
            uint32_t ah[4], al[4];
            uint32_t aoff = (a_row * TSTR + kk0 + a_koff) * 2;
            ldmx4(ah, uPH + aoff);
            ldmx4(al, uPL + aoff);
            #pragma unroll
            for (int ng = 0; ng < 2; ng++) {
                uint32_t bh2[4], bl2[4];
                uint32_t boff = ((b_row + ng * 16) * TSTR + kk0 + b_koff) * 2;
                ldmx4(bh2, sVH + boff);
                ldmx4(bl2, sVL + boff);
                mma_bf16(o[2*ng],   ah, bh2);
                mma_bf16(o[2*ng],   ah, bl2);
                mma_bf16(o[2*ng],   al, bh2);
                mma_bf16(o[2*ng+1], ah, bh2 + 2);
                mma_bf16(o[2*ng+1], ah, bl2 + 2);
                mma_bf16(o[2*ng+1], al, bh2 + 2);
            }
        }
        __syncthreads();
        if (s + 2 < 5) load_v(s + 2);
    }

    #pragma unroll
    for (int nt = 0; nt < 4; nt++) {
        #pragma unroll
        for (int half = 0; half < 2; half++) {
            int r = mw + (lane >> 2) + half * 8;
            int d = nw + nt * 8 + (lane & 3) * 2;
            float li = linv[r];
            float v0 = o[nt][half * 2 + 0] * li;
            float v1 = o[nt][half * 2 + 1] * li;
            __nv_bfloat16 h0, l0, h1, l1;
            split_bf16(v0, h0, l0);
            split_bf16(v1, h1, l1);
            size_t base = (size_t)(b * SEQ + t0 + r) * DIM + h * DH + d;
            __nv_bfloat162 hh; hh.x = h0; hh.y = h1;
            __nv_bfloat162 ll; ll.x = l0; ll.y = l1;
            *reinterpret_cast<__nv_bfloat162*>(oh + base) = hh;
            *reinterpret_cast<__nv_bfloat162*>(ol + base) = ll;
        }
    }
}

// ---------------- host launcher ----------------------------------------------
extern "C" void kernel_launch(void* const* d_in, const int* in_sizes, int n_in,
                              void* d_out, int out_size)
{
    const float* tokens = (const float*)d_in[0];
    const float* Wq = (const float*)d_in[1];
    const float* Wk = (const float*)d_in[2];
    const float* Wv = (const float*)d_in[3];
    const float* Wo = (const float*)d_in[4];
    const float* bq = (const float*)d_in[5];
    const float* bk = (const float*)d_in[6];
    const float* bv = (const float*)d_in[7];
    const float* bo = (const float*)d_in[8];
    const float* W1 = (const float*)d_in[9];
    const float* b1 = (const float*)d_in[10];
    const float* W2 = (const float*)d_in[11];
    const float* b2 = (const float*)d_in[12];
    const float* g1 = (const float*)d_in[13];
    const float* be1= (const float*)d_in[14];
    const float* g2 = (const float*)d_in[15];
    const float* be2= (const float*)d_in[16];
    const float* gf = (const float*)d_in[17];
    const float* bf = (const float*)d_in[18];

    float *x, *q, *k, *v;
    cudaGetSymbolAddress((void**)&x, g_x);
    cudaGetSymbolAddress((void**)&q, g_q);
    cudaGetSymbolAddress((void**)&k, g_k);
    cudaGetSymbolAddress((void**)&v, g_v);
    float* p0 = q;   // Wo/W2 partials reuse q/k (lifetimes disjoint)
    float* p1 = k;

    __nv_bfloat16 *xnh, *xnl, *atth, *attl, *hbh, *hbl;
    cudaGetSymbolAddress((void**)&xnh,  g_xnh);
    cudaGetSymbolAddress((void**)&xnl,  g_xnl);
    cudaGetSymbolAddress((void**)&atth, g_atth);
    cudaGetSymbolAddress((void**)&attl, g_attl);
    cudaGetSymbolAddress((void**)&hbh,  g_hbh);
    cudaGetSymbolAddress((void**)&hbl,  g_hbl);

    __nv_bfloat16 *qh, *ql, *kh, *kl, *vth, *vtl;
    cudaGetSymbolAddress((void**)&qh,  g_qh);
    cudaGetSymbolAddress((void**)&ql,  g_ql);
    cudaGetSymbolAddress((void**)&kh,  g_kh);
    cudaGetSymbolAddress((void**)&kl,  g_kl);
    cudaGetSymbolAddress((void**)&vth, g_vth);
    cudaGetSymbolAddress((void**)&vtl, g_vtl);

    __nv_bfloat16 *wqh,*wql,*wkh,*wkl,*wvh,*wvl,*woh,*wol,*w1h,*w1l,*w2h,*w2l;
    cudaGetSymbolAddress((void**)&wqh, g_wqt_h); cudaGetSymbolAddress((void**)&wql, g_wqt_l);
    cudaGetSymbolAddress((void**)&wkh, g_wkt_h); cudaGetSymbolAddress((void**)&wkl, g_wkt_l);
    cudaGetSymbolAddress((void**)&wvh, g_wvt_h); cudaGetSymbolAddress((void**)&wvl, g_wvt_l);
    cudaGetSymbolAddress((void**)&woh, g_wot_h); cudaGetSymbolAddress((void**)&wol, g_wot_l);
    cudaGetSymbolAddress((void**)&w1h, g_w1t_h); cudaGetSymbolAddress((void**)&w1l, g_w1t_l);
    cudaGetSymbolAddress((void**)&w2h, g_w2t_h); cudaGetSymbolAddress((void**)&w2l, g_w2t_l);

    cudaFuncSetAttribute(attn_kernel, cudaFuncAttributeMaxDynamicSharedMemorySize,
                         A3_BYTES);
    cudaFuncSetAttribute(qkv_mm, cudaFuncAttributeMaxDynamicSharedMemorySize, DSM_BYTES);
    cudaFuncSetAttribute(gemm_ksplit, cudaFuncAttributeMaxDynamicSharedMemorySize, DSM_BYTES);
    cudaFuncSetAttribute(gemm_mm<1,0,0,1>, cudaFuncAttributeMaxDynamicSharedMemorySize, DSM_BYTES);

    cudaMemcpyAsync(x, tokens, sizeof(float) * (size_t)BT * DIM,
                    cudaMemcpyDeviceToDevice, 0);

    // weight conversion
    {
        dim3 blk(32, 8);
        dim3 gdd(DIM / 32, DIM / 32, NL);
        wconv_kernel<<<gdd, blk>>>(Wq, wqh, wql, DIM, DIM);
        wconv_kernel<<<gdd, blk>>>(Wk, wkh, wkl, DIM, DIM);
        wconv_kernel<<<gdd, blk>>>(Wv, wvh, wvl, DIM, DIM);
        wconv_kernel<<<gdd, blk>>>(Wo, woh, wol, DIM, DIM);
        dim3 g1d(DFF / 32, DIM / 32, NL);
        wconv_kernel<<<g1d, blk>>>(W1, w1h, w1l, DIM, DFF);
        dim3 g2d(DIM / 32, DFF / 32, NL);
        wconv_kernel<<<g2d, blk>>>(W2, w2h, w2l, DFF, DIM);
    }

    dim3 gQKV(DIM / 128, BT / 128, 3);   // (4, 32, 3) full-K QKV
    dim3 gKS (DIM / 128, BT / 128, 2);   // split-K=2 for Wo/W2
    dim3 gF  (DFF / 128, BT / 128);
    dim3 gAtt(SEQ / QT, BATCH * NH);

    for (int l = 0; l < NL; l++) {
        size_t wofs  = (size_t)l * DIM * DIM;
        size_t w1ofs = (size_t)l * DIM * DFF;

        // ln1: fold previous layer's W2 partials (layers >= 1)
        const float* pp0 = (l == 0) ? nullptr : p0;
        const float* pp1 = (l == 0) ? nullptr : p1;
        float* xo = (l == 0) ? nullptr : x;
        ln_kernel<<<BT, 256>>>(x, pp0, pp1, g1 + l * DIM, be1 + l * DIM,
                               xo, nullptr, xnh, xnl);

        qkv_mm<<<gQKV, 256, DSM_BYTES>>>(xnh, xnl,
                                         wqh + wofs, wql + wofs,
                                         wkh + wofs, wkl + wofs,
                                         wvh + wofs, wvl + wofs,
                                         bq + l * DIM, bk + l * DIM, bv + l * DIM,
                                         q, k, v);

        // combined RoPE-split (q,k) + V transpose-split: 4096 + 2048 blocks
        qkvprep_kernel<<<PREP_BLOCKS, 256>>>(q, k, v, qh, ql, kh, kl, vth, vtl);

        attn_kernel<<<gAtt, 256, A3_BYTES>>>(qh, ql, kh, kl, vth, vtl, atth, attl);

        // Wo split-K=2 -> partials p0,p1 (q/k buffers now free)
        gemm_ksplit<<<gKS, 256, DSM_BYTES>>>(atth, attl, woh + wofs, wol + wofs,
                                             bo + l * DIM, p0, p1, DIM, DIM);

        // ln2: x = x + p0 + p1 (write back), then LN
        ln_kernel<<<BT, 256>>>(x, p0, p1, g2 + l * DIM, be2 + l * DIM,
                               x, nullptr, xnh, xnl);

        gemm_mm<1,0,0,1><<<gF, 256, DSM_BYTES>>>(xnh, xnl, w1h + w1ofs, w1l + w1ofs,
                                                 b1 + l * DFF, nullptr, nullptr, hbh, hbl,
                                                 DFF, DIM);

        // W2 split-K=2 -> partials p0,p1 (folded by next ln1 / final ln)
        gemm_ksplit<<<gKS, 256, DSM_BYTES>>>(hbh, hbl, w2h + w1ofs, w2l + w1ofs,
                                             b2 + l * DIM, p0, p1, DIM, DFF);
    }

    // final LN folds last W2 partials
    ln_kernel<<<BT, 256>>>(x, p0, p1, gf, bf, nullptr, (float*)d_out,
                           nullptr, nullptr);
}

// round 15
// speedup vs baseline: 1.0678x; 1.0521x over previous
#include <cuda_runtime.h>
#include <cuda_bf16.h>
#include <math.h>
#include <stdint.h>

#define BATCH 2
#define SEQ   2048
#define DIM   512
#define NH    8
#define DH    64
#define NL    4
#define DFF   2048
#define WIN   256
#define BT    (BATCH*SEQ)   // 4096

// ---------------- scratch (static device globals; no allocation) -------------
__device__ float g_x [BT*DIM];
__device__ float g_q [BT*DIM];    // q ; later Wo/W2 split-K partial 0
__device__ float g_k [BT*DIM];    // k ; later Wo/W2 split-K partial 1
__device__ float g_v [BT*DIM];

__device__ __nv_bfloat16 g_xnh [BT*DIM];
__device__ __nv_bfloat16 g_xnl [BT*DIM];
__device__ __nv_bfloat16 g_atth[BT*DIM];
__device__ __nv_bfloat16 g_attl[BT*DIM];
__device__ __nv_bfloat16 g_hbh [BT*DFF];
__device__ __nv_bfloat16 g_hbl [BT*DFF];

// attention operands (pre-split)
__device__ __nv_bfloat16 g_qh [BT*DIM], g_ql [BT*DIM];
__device__ __nv_bfloat16 g_kh [BT*DIM], g_kl [BT*DIM];
__device__ __nv_bfloat16 g_vth[BT*DIM], g_vtl[BT*DIM];   // [b*512+d][SEQ]

// transposed split weights: [L][N][K]
__device__ __nv_bfloat16 g_wqt_h[NL*DIM*DIM],  g_wqt_l[NL*DIM*DIM];
__device__ __nv_bfloat16 g_wkt_h[NL*DIM*DIM],  g_wkt_l[NL*DIM*DIM];
__device__ __nv_bfloat16 g_wvt_h[NL*DIM*DIM],  g_wvt_l[NL*DIM*DIM];
__device__ __nv_bfloat16 g_wot_h[NL*DIM*DIM],  g_wot_l[NL*DIM*DIM];
__device__ __nv_bfloat16 g_w1t_h[NL*DIM*DFF],  g_w1t_l[NL*DIM*DFF];
__device__ __nv_bfloat16 g_w2t_h[NL*DFF*DIM],  g_w2t_l[NL*DFF*DIM];

// ---------------- PTX helpers --------------------------------------------------
__device__ __forceinline__ uint32_t smem_u32(const void* p) {
    uint32_t a;
    asm("{ .reg .u64 t; cvta.to.shared.u64 t, %1; cvt.u32.u64 %0, t; }"
        : "=r"(a) : "l"(p));
    return a;
}

__device__ __forceinline__ void cpa16(uint32_t dst, const void* src)
{
    asm volatile("cp.async.cg.shared.global [%0], [%1], 16;" :: "r"(dst), "l"(src));
}

__device__ __forceinline__ void ldmx4(uint32_t* r, uint32_t addr)
{
    asm volatile("ldmatrix.sync.aligned.m8n8.x4.shared.b16 {%0,%1,%2,%3}, [%4];"
        : "=r"(r[0]), "=r"(r[1]), "=r"(r[2]), "=r"(r[3]) : "r"(addr));
}

__device__ __forceinline__ void mma_bf16(float* c, const uint32_t* a, const uint32_t* b)
{
    asm volatile(
        "mma.sync.aligned.m16n8k16.row.col.f32.bf16.bf16.f32 "
        "{%0,%1,%2,%3}, {%4,%5,%6,%7}, {%8,%9}, {%0,%1,%2,%3};"
        : "+f"(c[0]), "+f"(c[1]), "+f"(c[2]), "+f"(c[3])
        : "r"(a[0]), "r"(a[1]), "r"(a[2]), "r"(a[3]), "r"(b[0]), "r"(b[1]));
}

__device__ __forceinline__ void split_bf16(float v, __nv_bfloat16& h, __nv_bfloat16& l)
{
    h = __float2bfloat16(v);
    l = __float2bfloat16(v - __bfloat162float(h));
}

// ---------------- mma.sync bf16-split GEMM (2-stage, 2 CTAs/SM) ----------------
#define TKC       32
#define RSTR      40
#define ARR_BYTES (128*RSTR*2)
#define STG_BYTES (4*ARR_BYTES)       // 40960
#define DSM_BYTES (2*STG_BYTES)       // 81920 -> 2 CTAs/SM

template <int GELU, int RES, int OUTF32, int OUTBF>
__device__ __forceinline__ void gemm_mm_core(
    const __nv_bfloat16* __restrict__ Ah, const __nv_bfloat16* __restrict__ Al,
    const __nv_bfloat16* __restrict__ Bh, const __nv_bfloat16* __restrict__ Bl,
    const float* __restrict__ bias, const float* __restrict__ res,
    float* __restrict__ C, __nv_bfloat16* __restrict__ Oh, __nv_bfloat16* __restrict__ Ol,
    int N, int Kstr, int kbase, int Kloop, int m0, int n0)
{
    extern __shared__ char dsm[];
    uint32_t sm0 = smem_u32(dsm);

    int tid  = threadIdx.x;
    int wid  = tid >> 5, lane = tid & 31;
    int mw   = (wid & 3) * 32;
    int nw   = (wid >> 2) * 64;

    float acc[2][8][4];
    #pragma unroll
    for (int i = 0; i < 2; i++)
        #pragma unroll
        for (int j = 0; j < 8; j++)
            #pragma unroll
            for (int t = 0; t < 4; t++) acc[i][j][t] = 0.f;

    int nk = Kloop / TKC;

    auto load_stage = [&](int c) {
        uint32_t sb = sm0 + (c & 1) * STG_BYTES;
        int k0 = kbase + c * TKC;
        #pragma unroll
        for (int it = 0; it < 8; it++) {
            int idx  = it * 256 + tid;
            int arr  = idx >> 9;
            int rem  = idx & 511;
            int row  = rem >> 2;
            int part = rem & 3;
            uint32_t dst = sb + arr * ARR_BYTES + row * (RSTR * 2) + part * 16;
            const __nv_bfloat16* src;
            if      (arr == 0) src = Ah + (size_t)(m0 + row) * Kstr + k0 + part * 8;
            else if (arr == 1) src = Al + (size_t)(m0 + row) * Kstr + k0 + part * 8;
            else if (arr == 2) src = Bh + (size_t)(n0 + row) * Kstr + k0 + part * 8;
            else               src = Bl + (size_t)(n0 + row) * Kstr + k0 + part * 8;
            cpa16(dst, src);
        }
        asm volatile("cp.async.commit_group;" ::: "memory");
    };

    load_stage(0);

    int a_row = mw + (lane & 15);
    int a_koff = (lane >> 4) * 8;
    int b_row = nw + (lane & 7) + ((lane >> 4) & 1) * 8;
    int b_koff = ((lane >> 3) & 1) * 8;

    for (int c = 0; c < nk; c++) {
        asm volatile("cp.async.wait_group 0;" ::: "memory");
        __syncthreads();

        if (c + 1 < nk) load_stage(c + 1);

        uint32_t sb  = sm0 + (c & 1) * STG_BYTES;
        uint32_t sah = sb;
        uint32_t sal = sb + ARR_BYTES;
        uint32_t sbh = sb + 2 * ARR_BYTES;
        uint32_t sbl = sb + 3 * ARR_BYTES;

        #pragma unroll
        for (int h = 0; h < 2; h++) {
            int k0 = h * 16;
            uint32_t ah[2][4], al[2][4];
            #pragma unroll
            for (int mt = 0; mt < 2; mt++) {
                uint32_t off = ((a_row + mt * 16) * RSTR + k0 + a_koff) * 2;
                ldmx4(ah[mt], sah + off);
                ldmx4(al[mt], sal + off);
            }
            #pragma unroll
            for (int ng = 0; ng < 4; ng++) {
                uint32_t bh[4], bl[4];
                uint32_t off = ((b_row + ng * 16) * RSTR + k0 + b_koff) * 2;
                ldmx4(bh, sbh + off);
                ldmx4(bl, sbl + off);
                #pragma unroll
                for (int mt = 0; mt < 2; mt++) {
                    mma_bf16(acc[mt][2*ng],   ah[mt], bh);
                    mma_bf16(acc[mt][2*ng],   ah[mt], bl);
                    mma_bf16(acc[mt][2*ng],   al[mt], bh);
                    mma_bf16(acc[mt][2*ng+1], ah[mt], bh + 2);
                    mma_bf16(acc[mt][2*ng+1], ah[mt], bl + 2);
                    mma_bf16(acc[mt][2*ng+1], al[mt], bh + 2);
                }
            }
        }
        __syncthreads();
    }

    int cbase_n = n0 + nw + (lane & 3) * 2;
    #pragma unroll
    for (int mt = 0; mt < 2; mt++) {
        #pragma unroll
        for (int half = 0; half < 2; half++) {
            int row = m0 + mw + mt * 16 + (lane >> 2) + half * 8;
            size_t rbase = (size_t)row * N;
            #pragma unroll
            for (int nt = 0; nt < 8; nt++) {
                int col = cbase_n + nt * 8;
                float v0 = acc[mt][nt][half * 2 + 0];
                float v1 = acc[mt][nt][half * 2 + 1];
                if (bias) {
                    float2 b2 = *reinterpret_cast<const float2*>(bias + col);
                    v0 += b2.x; v1 += b2.y;
                }
                if (GELU) {
                    v0 = 0.5f * v0 * (1.0f + erff(v0 * 0.70710678118654752f));
                    v1 = 0.5f * v1 * (1.0f + erff(v1 * 0.70710678118654752f));
                }
                if (RES) {
                    float2 r2 = *reinterpret_cast<const float2*>(res + rbase + col);
                    v0 += r2.x; v1 += r2.y;
                }
                if (OUTF32) {
                    *reinterpret_cast<float2*>(C + rbase + col) = make_float2(v0, v1);
                }
                if (OUTBF) {
                    __nv_bfloat16 h0, l0, h1, l1;
                    split_bf16(v0, h0, l0);
                    split_bf16(v1, h1, l1);
                    __nv_bfloat162 hh; hh.x = h0; hh.y = h1;
                    __nv_bfloat162 ll; ll.x = l0; ll.y = l1;
                    *reinterpret_cast<__nv_bfloat162*>(Oh + rbase + col) = hh;
                    *reinterpret_cast<__nv_bfloat162*>(Ol + rbase + col) = ll;
                }
            }
        }
    }
}

// plain GEMM (full K)
template <int GELU, int RES, int OUTF32, int OUTBF>
__global__ void __launch_bounds__(256, 2)
gemm_mm(const __nv_bfloat16* __restrict__ Ah, const __nv_bfloat16* __restrict__ Al,
        const __nv_bfloat16* __restrict__ Bh, const __nv_bfloat16* __restrict__ Bl,
        const float* __restrict__ bias, const float* __restrict__ res,
        float* __restrict__ C, __nv_bfloat16* __restrict__ Oh,
        __nv_bfloat16* __restrict__ Ol, int N, int K)
{
    gemm_mm_core<GELU, RES, OUTF32, OUTBF>(Ah, Al, Bh, Bl, bias, res, C, Oh, Ol,
                                           N, K, 0, K, blockIdx.y * 128, blockIdx.x * 128);
}

// split-K=2 GEMM: grid.z selects k-half; writes fp32 partial (bias only in half 0)
__global__ void __launch_bounds__(256, 2)
gemm_ksplit(const __nv_bfloat16* __restrict__ Ah, const __nv_bfloat16* __restrict__ Al,
            const __nv_bfloat16* __restrict__ Bh, const __nv_bfloat16* __restrict__ Bl,
            const float* __restrict__ bias,
            float* __restrict__ p0, float* __restrict__ p1, int N, int K)
{
    int kz = blockIdx.z;
    float* C = kz ? p1 : p0;
    const float* bi = kz ? nullptr : bias;
    gemm_mm_core<0, 0, 1, 0>(Ah, Al, Bh, Bl, bi, nullptr, C, nullptr, nullptr,
                             N, K, kz * (K / 2), K / 2,
                             blockIdx.y * 128, blockIdx.x * 128);
}

// fused QKV (full K): grid.z selects output
__global__ void __launch_bounds__(256, 2)
qkv_mm(const __nv_bfloat16* __restrict__ Ah, const __nv_bfloat16* __restrict__ Al,
       const __nv_bfloat16* __restrict__ Bqh, const __nv_bfloat16* __restrict__ Bql,
       const __nv_bfloat16* __restrict__ Bkh, const __nv_bfloat16* __restrict__ Bkl,
       const __nv_bfloat16* __restrict__ Bvh, const __nv_bfloat16* __restrict__ Bvl,
       const float* __restrict__ bq, const float* __restrict__ bk,
       const float* __restrict__ bv,
       float* __restrict__ q, float* __restrict__ k, float* __restrict__ v)
{
    int z = blockIdx.z;
    const __nv_bfloat16* Bh = (z == 0) ? Bqh : (z == 1) ? Bkh : Bvh;
    const __nv_bfloat16* Bl = (z == 0) ? Bql : (z == 1) ? Bkl : Bvl;
    const float* bi = (z == 0) ? bq : (z == 1) ? bk : bv;
    float* C        = (z == 0) ? q  : (z == 1) ? k  : v;
    gemm_mm_core<0, 0, 1, 0>(Ah, Al, Bh, Bl, bi, nullptr, C, nullptr, nullptr,
                             DIM, DIM, 0, DIM, blockIdx.y * 128, blockIdx.x * 128);
}

// ---------------- weight transpose + bf16 split -------------------------------
__global__ void wconv_kernel(const float* __restrict__ W,
                             __nv_bfloat16* __restrict__ hiT,
                             __nv_bfloat16* __restrict__ loT, int K, int N)
{
    __shared__ float t[32][33];
    int n0 = blockIdx.x * 32, k0 = blockIdx.y * 32;
    size_t lofs = (size_t)blockIdx.z * K * N;
    const float* Wl = W + lofs;
    int tx = threadIdx.x, ty = threadIdx.y;
    #pragma unroll
    for (int i = 0; i < 4; i++)
        t[ty + 8 * i][tx] = Wl[(size_t)(k0 + ty + 8 * i) * N + n0 + tx];
    __syncthreads();
    __nv_bfloat16* ho = hiT + lofs;
    __nv_bfloat16* lo = loT + lofs;
    #pragma unroll
    for (int i = 0; i < 4; i++) {
        float v = t[tx][ty + 8 * i];
        __nv_bfloat16 h, l;
        split_bf16(v, h, l);
        ho[(size_t)(n0 + ty + 8 * i) * K + k0 + tx] = h;
        lo[(size_t)(n0 + ty + 8 * i) * K + k0 + tx] = l;
    }
}

// ---------------- combined qkv prep: RoPE-split (q,k) + V transpose-split ------
#define PREP_ROPE_BLOCKS ((BT*NH*32)/256)            // 4096
#define PREP_V_BLOCKS    ((SEQ/32)*(DIM/32)*BATCH)   // 2048
#define PREP_BLOCKS      (PREP_ROPE_BLOCKS + PREP_V_BLOCKS)

__global__ void __launch_bounds__(256)
qkvprep_kernel(const float* __restrict__ q, const float* __restrict__ k,
               const float* __restrict__ v,
               __nv_bfloat16* __restrict__ qh, __nv_bfloat16* __restrict__ ql,
               __nv_bfloat16* __restrict__ kh, __nv_bfloat16* __restrict__ kl,
               __nv_bfloat16* __restrict__ vth, __nv_bfloat16* __restrict__ vtl)
{
    int bid = blockIdx.x;
    int tid = threadIdx.x;

    if (bid < PREP_ROPE_BLOCKS) {
        int idx = bid * 256 + tid;          // over BT*NH*32
        int d  = idx & 31;
        int h  = (idx >> 5) & (NH - 1);
        int bt = idx >> 8;
        int t  = bt & (SEQ - 1);

        float inv_freq = __powf(10000.0f, -(float)(2 * d) / (float)DH);
        float ang = (float)t * inv_freq;
        float c, s;
        sincosf(ang, &s, &c);

        size_t base = (size_t)bt * DIM + h * DH + d;

        float q1 = q[base], q2 = q[base + 32];
        float qo1 = (q1 * c - q2 * s) * 0.125f;
        float qo2 = (q2 * c + q1 * s) * 0.125f;
        __nv_bfloat16 hh, ll;
        split_bf16(qo1, hh, ll); qh[base] = hh;      ql[base] = ll;
        split_bf16(qo2, hh, ll); qh[base + 32] = hh; ql[base + 32] = ll;

        float k1 = k[base], k2 = k[base + 32];
        float ko1 = k1 * c - k2 * s;
        float ko2 = k2 * c + k1 * s;
        split_bf16(ko1, hh, ll); kh[base] = hh;      kl[base] = ll;
        split_bf16(ko2, hh, ll); kh[base + 32] = hh; kl[base + 32] = ll;
    } else {
        __shared__ float t[32][33];
        int vb = bid - PREP_ROPE_BLOCKS;
        int t0 = (vb & 63) * 32;
        int d0 = ((vb >> 6) & 15) * 32;
        int b  = vb >> 10;
        int tx = tid & 31, ty = tid >> 5;
        #pragma unroll
        for (int i = 0; i < 4; i++)
            t[ty + 8 * i][tx] = v[(size_t)(b * SEQ + t0 + ty + 8 * i) * DIM + d0 + tx];
        __syncthreads();
        #pragma unroll
        for (int i = 0; i < 4; i++) {
            float val = t[tx][ty + 8 * i];
            __nv_bfloat16 h, l;
            split_bf16(val, h, l);
            size_t o = (size_t)(b * DIM + d0 + ty + 8 * i) * SEQ + t0 + tx;
            vth[o] = h;
            vtl[o] = l;
        }
    }
}

// ---------------- LayerNorm (optionally folds split-K partials) ----------------
__global__ void ln_kernel(const float* __restrict__ x,
                          const float* __restrict__ p0, const float* __restrict__ p1,
                          const float* __restrict__ g, const float* __restrict__ b,
                          float* __restrict__ xout, float* __restrict__ y,
                          __nv_bfloat16* __restrict__ yh, __nv_bfloat16* __restrict__ yl)
{
    int row = blockIdx.x;
    int tid = threadIdx.x;
    size_t base = (size_t)row * DIM;

    float v0 = x[base + tid];
    float v1 = x[base + tid + 256];
    if (p0) {
        v0 += p0[base + tid] + p1[base + tid];
        v1 += p0[base + tid + 256] + p1[base + tid + 256];
    }
    if (xout) {
        xout[base + tid]       = v0;
        xout[base + tid + 256] = v1;
    }

    float s  = v0 + v1;
    float ss = v0 * v0 + v1 * v1;
    #pragma unroll
    for (int o = 16; o; o >>= 1) {
        s  += __shfl_xor_sync(0xffffffffu, s,  o);
        ss += __shfl_xor_sync(0xffffffffu, ss, o);
    }
    __shared__ float ws[8], wss[8];
    int w = tid >> 5, ln = tid & 31;
    if (ln == 0) { ws[w] = s; wss[w] = ss; }
    __syncthreads();
    __shared__ float s_mu, s_rstd;
    if (tid == 0) {
        float S = 0.f, SS = 0.f;
        #pragma unroll
        for (int i = 0; i < 8; i++) { S += ws[i]; SS += wss[i]; }
        float mu  = S * (1.0f / DIM);
        float var = SS * (1.0f / DIM) - mu * mu;
        s_mu = mu; s_rstd = rsqrtf(var + 1e-5f);
    }
    __syncthreads();
    float mu = s_mu, rstd = s_rstd;
    float o0 = (v0 - mu) * rstd * g[tid]       + b[tid];
    float o1 = (v1 - mu) * rstd * g[tid + 256] + b[tid + 256];
    if (y) {
        y[base + tid]       = o0;
        y[base + tid + 256] = o1;
    }
    if (yh) {
        __nv_bfloat16 h0, l0, h1, l1;
        split_bf16(o0, h0, l0);
        split_bf16(o1, h1, l1);
        yh[base + tid]       = h0;
        yh[base + tid + 256] = h1;
        yl[base + tid]       = l0;
        yl[base + tid + 256] = l1;
    }
}

// ---------------- FA2-style mma attention (online softmax, 2 CTAs/SM) ---------
#define QT    64
#define TSTR  72
#define TILE_B (64*TSTR*2)     // 9216

// smem byte offsets
#define A4_QH   0
#define A4_QL   9216
#define A4_K    18432          // 2 bufs x (hi,lo) = 36864
#define A4_V    55296          // 36864
#define A4_P    92160          // hi,lo = 18432
#define A4_RED  110592         // redmax[128] + redsum[128] floats = 1024
#define A4_BYTES 111616

__global__ void __launch_bounds__(256, 2)
attn_kernel(const __nv_bfloat16* __restrict__ qh, const __nv_bfloat16* __restrict__ ql,
            const __nv_bfloat16* __restrict__ kh, const __nv_bfloat16* __restrict__ kl,
            const __nv_bfloat16* __restrict__ vth, const __nv_bfloat16* __restrict__ vtl,
            __nv_bfloat16* __restrict__ oh, __nv_bfloat16* __restrict__ ol)
{
    extern __shared__ char sm[];
    __nv_bfloat16* PH = (__nv_bfloat16*)(sm + A4_P);
    __nv_bfloat16* PL = (__nv_bfloat16*)(sm + A4_P + TILE_B);
    float* redmax = (float*)(sm + A4_RED);          // [2][64]
    float* redsum = (float*)(sm + A4_RED + 512);    // [2][64]

    uint32_t sb0 = smem_u32(sm);
    uint32_t uQH = sb0 + A4_QH;
    uint32_t uQL = sb0 + A4_QL;
    uint32_t uK  = sb0 + A4_K;
    uint32_t uV  = sb0 + A4_V;
    uint32_t uPH = sb0 + A4_P;
    uint32_t uPL = uPH + TILE_B;

    int tid  = threadIdx.x;
    int wid  = tid >> 5, lane = tid & 31;
    int mw   = (wid & 3) * 16;       // query rows
    int nw   = (wid >> 2) * 32;      // key cols / d cols
    int grp  = wid >> 2;             // 0 or 1

    int t0  = blockIdx.x * QT;
    int bh  = blockIdx.y;
    int b   = bh >> 3;
    int h   = bh & 7;
    int jbase = t0 - 256;

    int a_row  = mw + (lane & 15);
    int a_koff = (lane >> 4) * 8;
    int b_row  = nw + (lane & 7) + ((lane >> 4) & 1) * 8;
    int b_koff = ((lane >> 3) & 1) * 8;

    // Q load (shares commit group with kv(0))
    {
        #pragma unroll
        for (int it = 0; it < 4; it++) {
            int vi  = tid + 256 * it;
            int row = vi >> 4, c = vi & 15;
            const __nv_bfloat16* src = (c < 8 ? qh : ql)
                + (size_t)(b * SEQ + t0 + row) * DIM + h * DH + (c & 7) * 8;
            uint32_t dst = (c < 8 ? uQH : uQL) + row * (TSTR * 2) + (c & 7) * 16;
            cpa16(dst, src);
        }
    }

    auto load_kv = [&](int s) {
        int kb = jbase + s * 64;
        uint32_t kbuf = uK + (s & 1) * (2 * TILE_B);
        uint32_t vbuf = uV + (s & 1) * (2 * TILE_B);
        #pragma unroll
        for (int it = 0; it < 4; it++) {
            int vi  = tid + 256 * it;
            int row = vi >> 4, c = vi & 15;
            int j = kb + row;
            int jc = j < 0 ? 0 : j;
            const __nv_bfloat16* src = (c < 8 ? kh : kl)
                + (size_t)(b * SEQ + jc) * DIM + h * DH + (c & 7) * 8;
            uint32_t dst = kbuf + (c < 8 ? 0 : TILE_B) + row * (TSTR * 2) + (c & 7) * 16;
            cpa16(dst, src);
        }
        #pragma unroll
        for (int it = 0; it < 4; it++) {
            int vi  = tid + 256 * it;
            int row = vi >> 4, c = vi & 15;       // row = d (0..63)
            int j0 = kb + (c & 7) * 8;
            int jc = j0 < 0 ? 0 : j0;
            const __nv_bfloat16* src = (c < 8 ? vth : vtl)
                + (size_t)(b * DIM + h * DH + row) * SEQ + jc;
            uint32_t dst = vbuf + (c < 8 ? 0 : TILE_B) + row * (TSTR * 2) + (c & 7) * 16;
            cpa16(dst, src);
        }
        asm volatile("cp.async.commit_group;" ::: "memory");
    };

    load_kv(0);
    load_kv(1);

    float o[4][4];
    #pragma unroll
    for (int i = 0; i < 4; i++)
        #pragma unroll
        for (int j = 0; j < 4; j++) o[i][j] = 0.f;
    float m[2] = {-1e30f, -1e30f};
    float l[2] = {0.f, 0.f};

    int r0 = mw + (lane >> 2);   // half-0 row; half-1 row = r0+8

    for (int s = 0; s < 5; s++) {
        if (s < 4) asm volatile("cp.async.wait_group 1;" ::: "memory");
        else       asm volatile("cp.async.wait_group 0;" ::: "memory");
        __syncthreads();

        uint32_t sKH = uK + (s & 1) * (2 * TILE_B);
        uint32_t sKL = sKH + TILE_B;
        int kb = jbase + s * 64;

        // ---- QK^T ----
        float acc[4][4];
        #pragma unroll
        for (int i = 0; i < 4; i++)
            #pragma unroll
            for (int j = 0; j < 4; j++) acc[i][j] = 0.f;

        #pragma unroll
        for (int k16 = 0; k16 < 4; k16++) {
            int kk0 = k16 * 16;
            uint32_t ah[4], al[4];
            uint32_t aoff = (a_row * TSTR + kk0 + a_koff) * 2;
            ldmx4(ah, uQH + aoff);
            ldmx4(al, uQL + aoff);
            #pragma unroll
            for (int ng = 0; ng < 2; ng++) {
                uint32_t bh2[4], bl2[4];
                uint32_t boff = ((b_row + ng * 16) * TSTR + kk0 + b_koff) * 2;
                ldmx4(bh2, sKH + boff);
                ldmx4(bl2, sKL + boff);
                mma_bf16(acc[2*ng],   ah, bh2);
                mma_bf16(acc[2*ng],   ah, bl2);
                mma_bf16(acc[2*ng],   al, bh2);
                mma_bf16(acc[2*ng+1], ah, bh2 + 2);
                mma_bf16(acc[2*ng+1], ah, bl2 + 2);
                mma_bf16(acc[2*ng+1], al, bh2 + 2);
            }
        }

        // ---- mask + tile row max (warp part) ----
        float tmax[2] = {-INFINITY, -INFINITY};
        #pragma unroll
        for (int half = 0; half < 2; half++) {
            int r = r0 + half * 8;
            int ig = t0 + r;
            #pragma unroll
            for (int nt = 0; nt < 4; nt++) {
                #pragma unroll
                for (int e = 0; e < 2; e++) {
                    int jg = kb + nw + nt * 8 + (lane & 3) * 2 + e;
                    bool ok = (jg >= 0) && (jg <= ig) && (ig - jg < WIN);
                    float vv = ok ? acc[nt][half * 2 + e] : -INFINITY;
                    acc[nt][half * 2 + e] = vv;
                    tmax[half] = fmaxf(tmax[half], vv);
                }
            }
            tmax[half] = fmaxf(tmax[half], __shfl_xor_sync(0xffffffffu, tmax[half], 1));
            tmax[half] = fmaxf(tmax[half], __shfl_xor_sync(0xffffffffu, tmax[half], 2));
        }
        if ((lane & 3) == 0) {
            redmax[grp * 64 + r0]     = tmax[0];
            redmax[grp * 64 + r0 + 8] = tmax[1];
        }
        __syncthreads();

        // ---- online update: m, rescale o; compute P; write P; partial sums ----
        float tsum[2] = {0.f, 0.f};
        #pragma unroll
        for (int half = 0; half < 2; half++) {
            int r = r0 + half * 8;
            float tm = fmaxf(redmax[r], redmax[64 + r]);
            float mn = fmaxf(m[half], tm);
            float sc = __expf(m[half] - mn);
            m[half] = mn;
            l[half] *= sc;
            #pragma unroll
            for (int nt = 0; nt < 4; nt++) {
                o[nt][half * 2 + 0] *= sc;
                o[nt][half * 2 + 1] *= sc;
                float p0v = __expf(acc[nt][half * 2 + 0] - mn);
                float p1v = __expf(acc[nt][half * 2 + 1] - mn);
                tsum[half] += p0v + p1v;
                __nv_bfloat16 h0, l0b, h1, l1b;
                split_bf16(p0v, h0, l0b);
                split_bf16(p1v, h1, l1b);
                __nv_bfloat162 hh; hh.x = h0; hh.y = h1;
                __nv_bfloat162 ll; ll.x = l0b; ll.y = l1b;
                int off = r * TSTR + nw + nt * 8 + (lane & 3) * 2;
                *reinterpret_cast<__nv_bfloat162*>(PH + off) = hh;
                *reinterpret_cast<__nv_bfloat162*>(PL + off) = ll;
            }
            tsum[half] += __shfl_xor_sync(0xffffffffu, tsum[half], 1);
            tsum[half] += __shfl_xor_sync(0xffffffffu, tsum[half], 2);
        }
        if ((lane & 3) == 0) {
            redsum[grp * 64 + r0]     = tsum[0];
            redsum[grp * 64 + r0 + 8] = tsum[1];
        }
        __syncthreads();   // P visible + sums visible

        l[0] += redsum[r0]     + redsum[64 + r0];
        l[1] += redsum[r0 + 8] + redsum[64 + r0 + 8];

        // ---- PV ----
        uint32_t sVH = uV + (s & 1) * (2 * TILE_B);
        uint32_t sVL = sVH + TILE_B;
        #pragma unroll
        for (int k16 = 0; k16 < 4; k16++) {
            int kk0 = k16 * 16;
            uint32_t ah[4], al[4];
            uint32_t aoff = (a_row * TSTR + kk0 + a_koff) * 2;
            ldmx4(ah, uPH + aoff);
            ldmx4(al, uPL + aoff);
            #pragma unroll
            for (int ng = 0; ng < 2; ng++) {
                uint32_t bh2[4], bl2[4];
                uint32_t boff = ((b_row + ng * 16) * TSTR + kk0 + b_koff) * 2;
                ldmx4(bh2, sVH + boff);
                ldmx4(bl2, sVL + boff);
                mma_bf16(o[2*ng],   ah, bh2);
                mma_bf16(o[2*ng],   ah, bl2);
                mma_bf16(o[2*ng],   al, bh2);
                mma_bf16(o[2*ng+1], ah, bh2 + 2);
                mma_bf16(o[2*ng+1], ah, bl2 + 2);
                mma_bf16(o[2*ng+1], al, bh2 + 2);
            }
        }
        __syncthreads();   // K/V bufs + P free for reuse
        if (s + 2 < 5) load_kv(s + 2);
    }

    // ---- write out ----
    float li[2] = {1.0f / l[0], 1.0f / l[1]};
    #pragma unroll
    for (int nt = 0; nt < 4; nt++) {
        #pragma unroll
        for (int half = 0; half < 2; half++) {
            int r = r0 + half * 8;
            int d = nw + nt * 8 + (lane & 3) * 2;
            float v0 = o[nt][half * 2 + 0] * li[half];
            float v1 = o[nt][half * 2 + 1] * li[half];
            __nv_bfloat16 h0, l0b, h1, l1b;
            split_bf16(v0, h0, l0b);
            split_bf16(v1, h1, l1b);
            size_t base = (size_t)(b * SEQ + t0 + r) * DIM + h * DH + d;
            __nv_bfloat162 hh; hh.x = h0; hh.y = h1;
            __nv_bfloat162 ll; ll.x = l0b; ll.y = l1b;
            *reinterpret_cast<__nv_bfloat162*>(oh + base) = hh;
            *reinterpret_cast<__nv_bfloat162*>(ol + base) = ll;
        }
    }
}

// ---------------- host launcher ----------------------------------------------
extern "C" void kernel_launch(void* const* d_in, const int* in_sizes, int n_in,
                              void* d_out, int out_size)
{
    const float* tokens = (const float*)d_in[0];
    const float* Wq = (const float*)d_in[1];
    const float* Wk = (const float*)d_in[2];
    const float* Wv = (const float*)d_in[3];
    const float* Wo = (const float*)d_in[4];
    const float* bq = (const float*)d_in[5];
    const float* bk = (const float*)d_in[6];
    const float* bv = (const float*)d_in[7];
    const float* bo = (const float*)d_in[8];
    const float* W1 = (const float*)d_in[9];
    const float* b1 = (const float*)d_in[10];
    const float* W2 = (const float*)d_in[11];
    const float* b2 = (const float*)d_in[12];
    const float* g1 = (const float*)d_in[13];
    const float* be1= (const float*)d_in[14];
    const float* g2 = (const float*)d_in[15];
    const float* be2= (const float*)d_in[16];
    const float* gf = (const float*)d_in[17];
    const float* bf = (const float*)d_in[18];

    float *x, *q, *k, *v;
    cudaGetSymbolAddress((void**)&x, g_x);
    cudaGetSymbolAddress((void**)&q, g_q);
    cudaGetSymbolAddress((void**)&k, g_k);
    cudaGetSymbolAddress((void**)&v, g_v);
    float* p0 = q;
    float* p1 = k;

    __nv_bfloat16 *xnh, *xnl, *atth, *attl, *hbh, *hbl;
    cudaGetSymbolAddress((void**)&xnh,  g_xnh);
    cudaGetSymbolAddress((void**)&xnl,  g_xnl);
    cudaGetSymbolAddress((void**)&atth, g_atth);
    cudaGetSymbolAddress((void**)&attl, g_attl);
    cudaGetSymbolAddress((void**)&hbh,  g_hbh);
    cudaGetSymbolAddress((void**)&hbl,  g_hbl);

    __nv_bfloat16 *qh, *ql, *kh, *kl, *vth, *vtl;
    cudaGetSymbolAddress((void**)&qh,  g_qh);
    cudaGetSymbolAddress((void**)&ql,  g_ql);
    cudaGetSymbolAddress((void**)&kh,  g_kh);
    cudaGetSymbolAddress((void**)&kl,  g_kl);
    cudaGetSymbolAddress((void**)&vth, g_vth);
    cudaGetSymbolAddress((void**)&vtl, g_vtl);

    __nv_bfloat16 *wqh,*wql,*wkh,*wkl,*wvh,*wvl,*woh,*wol,*w1h,*w1l,*w2h,*w2l;
    cudaGetSymbolAddress((void**)&wqh, g_wqt_h); cudaGetSymbolAddress((void**)&wql, g_wqt_l);
    cudaGetSymbolAddress((void**)&wkh, g_wkt_h); cudaGetSymbolAddress((void**)&wkl, g_wkt_l);
    cudaGetSymbolAddress((void**)&wvh, g_wvt_h); cudaGetSymbolAddress((void**)&wvl, g_wvt_l);
    cudaGetSymbolAddress((void**)&woh, g_wot_h); cudaGetSymbolAddress((void**)&wol, g_wot_l);
    cudaGetSymbolAddress((void**)&w1h, g_w1t_h); cudaGetSymbolAddress((void**)&w1l, g_w1t_l);
    cudaGetSymbolAddress((void**)&w2h, g_w2t_h); cudaGetSymbolAddress((void**)&w2l, g_w2t_l);

    cudaFuncSetAttribute(attn_kernel, cudaFuncAttributeMaxDynamicSharedMemorySize,
                         A4_BYTES);
    cudaFuncSetAttribute(qkv_mm, cudaFuncAttributeMaxDynamicSharedMemorySize, DSM_BYTES);
    cudaFuncSetAttribute(gemm_ksplit, cudaFuncAttributeMaxDynamicSharedMemorySize, DSM_BYTES);
    cudaFuncSetAttribute(gemm_mm<1,0,0,1>, cudaFuncAttributeMaxDynamicSharedMemorySize, DSM_BYTES);

    cudaMemcpyAsync(x, tokens, sizeof(float) * (size_t)BT * DIM,
                    cudaMemcpyDeviceToDevice, 0);

    // weight conversion
    {
        dim3 blk(32, 8);
        dim3 gdd(DIM / 32, DIM / 32, NL);
        wconv_kernel<<<gdd, blk>>>(Wq, wqh, wql, DIM, DIM);
        wconv_kernel<<<gdd, blk>>>(Wk, wkh, wkl, DIM, DIM);
        wconv_kernel<<<gdd, blk>>>(Wv, wvh, wvl, DIM, DIM);
        wconv_kernel<<<gdd, blk>>>(Wo, woh, wol, DIM, DIM);
        dim3 g1d(DFF / 32, DIM / 32, NL);
        wconv_kernel<<<g1d, blk>>>(W1, w1h, w1l, DIM, DFF);
        dim3 g2d(DIM / 32, DFF / 32, NL);
        wconv_kernel<<<g2d, blk>>>(W2, w2h, w2l, DFF, DIM);
    }

    dim3 gQKV(DIM / 128, BT / 128, 3);
    dim3 gKS (DIM / 128, BT / 128, 2);
    dim3 gF  (DFF / 128, BT / 128);
    dim3 gAtt(SEQ / QT, BATCH * NH);

    for (int l = 0; l < NL; l++) {
        size_t wofs  = (size_t)l * DIM * DIM;
        size_t w1ofs = (size_t)l * DIM * DFF;

        const float* pp0 = (l == 0) ? nullptr : p0;
        const float* pp1 = (l == 0) ? nullptr : p1;
        float* xo = (l == 0) ? nullptr : x;
        ln_kernel<<<BT, 256>>>(x, pp0, pp1, g1 + l * DIM, be1 + l * DIM,
                               xo, nullptr, xnh, xnl);

        qkv_mm<<<gQKV, 256, DSM_BYTES>>>(xnh, xnl,
                                         wqh + wofs, wql + wofs,
                                         wkh + wofs, wkl + wofs,
                                         wvh + wofs, wvl + wofs,
                                         bq + l * DIM, bk + l * DIM, bv + l * DIM,
                                         q, k, v);

        qkvprep_kernel<<<PREP_BLOCKS, 256>>>(q, k, v, qh, ql, kh, kl, vth, vtl);

        attn_kernel<<<gAtt, 256, A4_BYTES>>>(qh, ql, kh, kl, vth, vtl, atth, attl);

        gemm_ksplit<<<gKS, 256, DSM_BYTES>>>(atth, attl, woh + wofs, wol + wofs,
                                             bo + l * DIM, p0, p1, DIM, DIM);

        ln_kernel<<<BT, 256>>>(x, p0, p1, g2 + l * DIM, be2 + l * DIM,
                               x, nullptr, xnh, xnl);

        gemm_mm<1,0,0,1><<<gF, 256, DSM_BYTES>>>(xnh, xnl, w1h + w1ofs, w1l + w1ofs,
                                                 b1 + l * DFF, nullptr, nullptr, hbh, hbl,
                                                 DFF, DIM);

        gemm_ksplit<<<gKS, 256, DSM_BYTES>>>(hbh, hbl, w2h + w1ofs, w2l + w1ofs,
                                             b2 + l * DIM, p0, p1, DIM, DFF);
    }

    ln_kernel<<<BT, 256>>>(x, p0, p1, gf, bf, nullptr, (float*)d_out,
                           nullptr, nullptr);
}

// round 16
// speedup vs baseline: 1.0734x; 1.0053x over previous
#include <cuda_runtime.h>
#include <cuda_bf16.h>
#include <math.h>
#include <stdint.h>

#define BATCH 2
#define SEQ   2048
#define DIM   512
#define NH    8
#define DH    64
#define NL    4
#define DFF   2048
#define WIN   256
#define BT    (BATCH*SEQ)   // 4096

// ---------------- scratch (static device globals; no allocation) -------------
__device__ float g_x [BT*DIM];
__device__ float g_q [BT*DIM];    // q ; later Wo/W2 split-K partial 0
__device__ float g_k [BT*DIM];    // k ; later Wo/W2 split-K partial 1
__device__ float g_v [BT*DIM];

__device__ __nv_bfloat16 g_xnh [BT*DIM];
__device__ __nv_bfloat16 g_xnl [BT*DIM];
__device__ __nv_bfloat16 g_atth[BT*DIM];
__device__ __nv_bfloat16 g_attl[BT*DIM];
__device__ __nv_bfloat16 g_hbh [BT*DFF];
__device__ __nv_bfloat16 g_hbl [BT*DFF];

// attention operands (pre-split)
__device__ __nv_bfloat16 g_qh [BT*DIM], g_ql [BT*DIM];
__device__ __nv_bfloat16 g_kh [BT*DIM], g_kl [BT*DIM];
__device__ __nv_bfloat16 g_vth[BT*DIM], g_vtl[BT*DIM];   // [b*512+d][SEQ]

// transposed split weights: [L][N][K]
__device__ __nv_bfloat16 g_wqt_h[NL*DIM*DIM],  g_wqt_l[NL*DIM*DIM];
__device__ __nv_bfloat16 g_wkt_h[NL*DIM*DIM],  g_wkt_l[NL*DIM*DIM];
__device__ __nv_bfloat16 g_wvt_h[NL*DIM*DIM],  g_wvt_l[NL*DIM*DIM];
__device__ __nv_bfloat16 g_wot_h[NL*DIM*DIM],  g_wot_l[NL*DIM*DIM];
__device__ __nv_bfloat16 g_w1t_h[NL*DIM*DFF],  g_w1t_l[NL*DIM*DFF];
__device__ __nv_bfloat16 g_w2t_h[NL*DFF*DIM],  g_w2t_l[NL*DFF*DIM];

// ---------------- PTX helpers --------------------------------------------------
__device__ __forceinline__ uint32_t smem_u32(const void* p) {
    uint32_t a;
    asm("{ .reg .u64 t; cvta.to.shared.u64 t, %1; cvt.u32.u64 %0, t; }"
        : "=r"(a) : "l"(p));
    return a;
}

__device__ __forceinline__ void cpa16(uint32_t dst, const void* src)
{
    asm volatile("cp.async.cg.shared.global [%0], [%1], 16;" :: "r"(dst), "l"(src));
}

__device__ __forceinline__ void ldmx4(uint32_t* r, uint32_t addr)
{
    asm volatile("ldmatrix.sync.aligned.m8n8.x4.shared.b16 {%0,%1,%2,%3}, [%4];"
        : "=r"(r[0]), "=r"(r[1]), "=r"(r[2]), "=r"(r[3]) : "r"(addr));
}

__device__ __forceinline__ void mma_bf16(float* c, const uint32_t* a, const uint32_t* b)
{
    asm volatile(
        "mma.sync.aligned.m16n8k16.row.col.f32.bf16.bf16.f32 "
        "{%0,%1,%2,%3}, {%4,%5,%6,%7}, {%8,%9}, {%0,%1,%2,%3};"
        : "+f"(c[0]), "+f"(c[1]), "+f"(c[2]), "+f"(c[3])
        : "r"(a[0]), "r"(a[1]), "r"(a[2]), "r"(a[3]), "r"(b[0]), "r"(b[1]));
}

__device__ __forceinline__ void split_bf16(float v, __nv_bfloat16& h, __nv_bfloat16& l)
{
    h = __float2bfloat16(v);
    l = __float2bfloat16(v - __bfloat162float(h));
}

// ---------------- mma.sync bf16-split GEMM (2-stage, 2 CTAs/SM) ----------------
#define TKC       32
#define RSTR      40
#define ARR_BYTES (128*RSTR*2)
#define STG_BYTES (4*ARR_BYTES)       // 40960
#define DSM_BYTES (2*STG_BYTES)       // 81920 -> 2 CTAs/SM

template <int GELU, int RES, int OUTF32, int OUTBF>
__device__ __forceinline__ void gemm_mm_core(
    const __nv_bfloat16* __restrict__ Ah, const __nv_bfloat16* __restrict__ Al,
    const __nv_bfloat16* __restrict__ Bh, const __nv_bfloat16* __restrict__ Bl,
    const float* __restrict__ bias, const float* __restrict__ res,
    float* __restrict__ C, __nv_bfloat16* __restrict__ Oh, __nv_bfloat16* __restrict__ Ol,
    int N, int Kstr, int kbase, int Kloop, int m0, int n0)
{
    extern __shared__ char dsm[];
    uint32_t sm0 = smem_u32(dsm);

    int tid  = threadIdx.x;
    int wid  = tid >> 5, lane = tid & 31;
    int mw   = (wid & 3) * 32;
    int nw   = (wid >> 2) * 64;

    float acc[2][8][4];
    #pragma unroll
    for (int i = 0; i < 2; i++)
        #pragma unroll
        for (int j = 0; j < 8; j++)
            #pragma unroll
            for (int t = 0; t < 4; t++) acc[i][j][t] = 0.f;

    int nk = Kloop / TKC;

    auto load_stage = [&](int c) {
        uint32_t sb = sm0 + (c & 1) * STG_BYTES;
        int k0 = kbase + c * TKC;
        #pragma unroll
        for (int it = 0; it < 8; it++) {
            int idx  = it * 256 + tid;
            int arr  = idx >> 9;
            int rem  = idx & 511;
            int row  = rem >> 2;
            int part = rem & 3;
            uint32_t dst = sb + arr * ARR_BYTES + row * (RSTR * 2) + part * 16;
            const __nv_bfloat16* src;
            if      (arr == 0) src = Ah + (size_t)(m0 + row) * Kstr + k0 + part * 8;
            else if (arr == 1) src = Al + (size_t)(m0 + row) * Kstr + k0 + part * 8;
            else if (arr == 2) src = Bh + (size_t)(n0 + row) * Kstr + k0 + part * 8;
            else               src = Bl + (size_t)(n0 + row) * Kstr + k0 + part * 8;
            cpa16(dst, src);
        }
        asm volatile("cp.async.commit_group;" ::: "memory");
    };

    load_stage(0);

    int a_row = mw + (lane & 15);
    int a_koff = (lane >> 4) * 8;
    int b_row = nw + (lane & 7) + ((lane >> 4) & 1) * 8;
    int b_koff = ((lane >> 3) & 1) * 8;

    for (int c = 0; c < nk; c++) {
        asm volatile("cp.async.wait_group 0;" ::: "memory");
        __syncthreads();

        if (c + 1 < nk) load_stage(c + 1);

        uint32_t sb  = sm0 + (c & 1) * STG_BYTES;
        uint32_t sah = sb;
        uint32_t sal = sb + ARR_BYTES;
        uint32_t sbh = sb + 2 * ARR_BYTES;
        uint32_t sbl = sb + 3 * ARR_BYTES;

        #pragma unroll
        for (int h = 0; h < 2; h++) {
            int k0 = h * 16;
            uint32_t ah[2][4], al[2][4];
            #pragma unroll
            for (int mt = 0; mt < 2; mt++) {
                uint32_t off = ((a_row + mt * 16) * RSTR + k0 + a_koff) * 2;
                ldmx4(ah[mt], sah + off);
                ldmx4(al[mt], sal + off);
            }
            #pragma unroll
            for (int ng = 0; ng < 4; ng++) {
                uint32_t bh[4], bl[4];
                uint32_t off = ((b_row + ng * 16) * RSTR + k0 + b_koff) * 2;
                ldmx4(bh, sbh + off);
                ldmx4(bl, sbl + off);
                #pragma unroll
                for (int mt = 0; mt < 2; mt++) {
                    mma_bf16(acc[mt][2*ng],   ah[mt], bh);
                    mma_bf16(acc[mt][2*ng],   ah[mt], bl);
                    mma_bf16(acc[mt][2*ng],   al[mt], bh);
                    mma_bf16(acc[mt][2*ng+1], ah[mt], bh + 2);
                    mma_bf16(acc[mt][2*ng+1], ah[mt], bl + 2);
                    mma_bf16(acc[mt][2*ng+1], al[mt], bh + 2);
                }
            }
        }
        __syncthreads();
    }

    int cbase_n = n0 + nw + (lane & 3) * 2;
    #pragma unroll
    for (int mt = 0; mt < 2; mt++) {
        #pragma unroll
        for (int half = 0; half < 2; half++) {
            int row = m0 + mw + mt * 16 + (lane >> 2) + half * 8;
            size_t rbase = (size_t)row * N;
            #pragma unroll
            for (int nt = 0; nt < 8; nt++) {
                int col = cbase_n + nt * 8;
                float v0 = acc[mt][nt][half * 2 + 0];
                float v1 = acc[mt][nt][half * 2 + 1];
                if (bias) {
                    float2 b2 = *reinterpret_cast<const float2*>(bias + col);
                    v0 += b2.x; v1 += b2.y;
                }
                if (GELU) {
                    v0 = 0.5f * v0 * (1.0f + erff(v0 * 0.70710678118654752f));
                    v1 = 0.5f * v1 * (1.0f + erff(v1 * 0.70710678118654752f));
                }
                if (RES) {
                    float2 r2 = *reinterpret_cast<const float2*>(res + rbase + col);
                    v0 += r2.x; v1 += r2.y;
                }
                if (OUTF32) {
                    *reinterpret_cast<float2*>(C + rbase + col) = make_float2(v0, v1);
                }
                if (OUTBF) {
                    __nv_bfloat16 h0, l0, h1, l1;
                    split_bf16(v0, h0, l0);
                    split_bf16(v1, h1, l1);
                    __nv_bfloat162 hh; hh.x = h0; hh.y = h1;
                    __nv_bfloat162 ll; ll.x = l0; ll.y = l1;
                    *reinterpret_cast<__nv_bfloat162*>(Oh + rbase + col) = hh;
                    *reinterpret_cast<__nv_bfloat162*>(Ol + rbase + col) = ll;
                }
            }
        }
    }
}

// plain GEMM (full K)
template <int GELU, int RES, int OUTF32, int OUTBF>
__global__ void __launch_bounds__(256, 2)
gemm_mm(const __nv_bfloat16* __restrict__ Ah, const __nv_bfloat16* __restrict__ Al,
        const __nv_bfloat16* __restrict__ Bh, const __nv_bfloat16* __restrict__ Bl,
        const float* __restrict__ bias, const float* __restrict__ res,
        float* __restrict__ C, __nv_bfloat16* __restrict__ Oh,
        __nv_bfloat16* __restrict__ Ol, int N, int K)
{
    gemm_mm_core<GELU, RES, OUTF32, OUTBF>(Ah, Al, Bh, Bl, bias, res, C, Oh, Ol,
                                           N, K, 0, K, blockIdx.y * 128, blockIdx.x * 128);
}

// split-K=2 GEMM: grid.z selects k-half; writes fp32 partial (bias only in half 0)
__global__ void __launch_bounds__(256, 2)
gemm_ksplit(const __nv_bfloat16* __restrict__ Ah, const __nv_bfloat16* __restrict__ Al,
            const __nv_bfloat16* __restrict__ Bh, const __nv_bfloat16* __restrict__ Bl,
            const float* __restrict__ bias,
            float* __restrict__ p0, float* __restrict__ p1, int N, int K)
{
    int kz = blockIdx.z;
    float* C = kz ? p1 : p0;
    const float* bi = kz ? nullptr : bias;
    gemm_mm_core<0, 0, 1, 0>(Ah, Al, Bh, Bl, bi, nullptr, C, nullptr, nullptr,
                             N, K, kz * (K / 2), K / 2,
                             blockIdx.y * 128, blockIdx.x * 128);
}

// fused QKV (full K): grid.z selects output
__global__ void __launch_bounds__(256, 2)
qkv_mm(const __nv_bfloat16* __restrict__ Ah, const __nv_bfloat16* __restrict__ Al,
       const __nv_bfloat16* __restrict__ Bqh, const __nv_bfloat16* __restrict__ Bql,
       const __nv_bfloat16* __restrict__ Bkh, const __nv_bfloat16* __restrict__ Bkl,
       const __nv_bfloat16* __restrict__ Bvh, const __nv_bfloat16* __restrict__ Bvl,
       const float* __restrict__ bq, const float* __restrict__ bk,
       const float* __restrict__ bv,
       float* __restrict__ q, float* __restrict__ k, float* __restrict__ v)
{
    int z = blockIdx.z;
    const __nv_bfloat16* Bh = (z == 0) ? Bqh : (z == 1) ? Bkh : Bvh;
    const __nv_bfloat16* Bl = (z == 0) ? Bql : (z == 1) ? Bkl : Bvl;
    const float* bi = (z == 0) ? bq : (z == 1) ? bk : bv;
    float* C        = (z == 0) ? q  : (z == 1) ? k  : v;
    gemm_mm_core<0, 0, 1, 0>(Ah, Al, Bh, Bl, bi, nullptr, C, nullptr, nullptr,
                             DIM, DIM, 0, DIM, blockIdx.y * 128, blockIdx.x * 128);
}

// ---------------- weight transpose + bf16 split -------------------------------
__global__ void wconv_kernel(const float* __restrict__ W,
                             __nv_bfloat16* __restrict__ hiT,
                             __nv_bfloat16* __restrict__ loT, int K, int N)
{
    __shared__ float t[32][33];
    int n0 = blockIdx.x * 32, k0 = blockIdx.y * 32;
    size_t lofs = (size_t)blockIdx.z * K * N;
    const float* Wl = W + lofs;
    int tx = threadIdx.x, ty = threadIdx.y;
    #pragma unroll
    for (int i = 0; i < 4; i++)
        t[ty + 8 * i][tx] = Wl[(size_t)(k0 + ty + 8 * i) * N + n0 + tx];
    __syncthreads();
    __nv_bfloat16* ho = hiT + lofs;
    __nv_bfloat16* lo = loT + lofs;
    #pragma unroll
    for (int i = 0; i < 4; i++) {
        float v = t[tx][ty + 8 * i];
        __nv_bfloat16 h, l;
        split_bf16(v, h, l);
        ho[(size_t)(n0 + ty + 8 * i) * K + k0 + tx] = h;
        lo[(size_t)(n0 + ty + 8 * i) * K + k0 + tx] = l;
    }
}

// ---------------- combined qkv prep: RoPE-split (q,k) + V transpose-split ------
#define PREP_ROPE_BLOCKS ((BT*NH*32)/256)            // 4096
#define PREP_V_BLOCKS    ((SEQ/32)*(DIM/32)*BATCH)   // 2048
#define PREP_BLOCKS      (PREP_ROPE_BLOCKS + PREP_V_BLOCKS)

__global__ void __launch_bounds__(256)
qkvprep_kernel(const float* __restrict__ q, const float* __restrict__ k,
               const float* __restrict__ v,
               __nv_bfloat16* __restrict__ qh, __nv_bfloat16* __restrict__ ql,
               __nv_bfloat16* __restrict__ kh, __nv_bfloat16* __restrict__ kl,
               __nv_bfloat16* __restrict__ vth, __nv_bfloat16* __restrict__ vtl)
{
    int bid = blockIdx.x;
    int tid = threadIdx.x;

    if (bid < PREP_ROPE_BLOCKS) {
        int idx = bid * 256 + tid;          // over BT*NH*32
        int d  = idx & 31;
        int h  = (idx >> 5) & (NH - 1);
        int bt = idx >> 8;
        int t  = bt & (SEQ - 1);

        float inv_freq = __powf(10000.0f, -(float)(2 * d) / (float)DH);
        float ang = (float)t * inv_freq;
        float c, s;
        sincosf(ang, &s, &c);

        size_t base = (size_t)bt * DIM + h * DH + d;

        float q1 = q[base], q2 = q[base + 32];
        float qo1 = (q1 * c - q2 * s) * 0.125f;
        float qo2 = (q2 * c + q1 * s) * 0.125f;
        __nv_bfloat16 hh, ll;
        split_bf16(qo1, hh, ll); qh[base] = hh;      ql[base] = ll;
        split_bf16(qo2, hh, ll); qh[base + 32] = hh; ql[base + 32] = ll;

        float k1 = k[base], k2 = k[base + 32];
        float ko1 = k1 * c - k2 * s;
        float ko2 = k2 * c + k1 * s;
        split_bf16(ko1, hh, ll); kh[base] = hh;      kl[base] = ll;
        split_bf16(ko2, hh, ll); kh[base + 32] = hh; kl[base + 32] = ll;
    } else {
        __shared__ float t[32][33];
        int vb = bid - PREP_ROPE_BLOCKS;
        int t0 = (vb & 63) * 32;
        int d0 = ((vb >> 6) & 15) * 32;
        int b  = vb >> 10;
        int tx = tid & 31, ty = tid >> 5;
        #pragma unroll
        for (int i = 0; i < 4; i++)
            t[ty + 8 * i][tx] = v[(size_t)(b * SEQ + t0 + ty + 8 * i) * DIM + d0 + tx];
        __syncthreads();
        #pragma unroll
        for (int i = 0; i < 4; i++) {
            float val = t[tx][ty + 8 * i];
            __nv_bfloat16 h, l;
            split_bf16(val, h, l);
            size_t o = (size_t)(b * DIM + d0 + ty + 8 * i) * SEQ + t0 + tx;
            vth[o] = h;
            vtl[o] = l;
        }
    }
}

// ---------------- LayerNorm (optionally folds split-K partials) ----------------
__global__ void ln_kernel(const float* __restrict__ x,
                          const float* __restrict__ p0, const float* __restrict__ p1,
                          const float* __restrict__ g, const float* __restrict__ b,
                          float* __restrict__ xout, float* __restrict__ y,
                          __nv_bfloat16* __restrict__ yh, __nv_bfloat16* __restrict__ yl)
{
    int row = blockIdx.x;
    int tid = threadIdx.x;
    size_t base = (size_t)row * DIM;

    float v0 = x[base + tid];
    float v1 = x[base + tid + 256];
    if (p0) {
        v0 += p0[base + tid] + p1[base + tid];
        v1 += p0[base + tid + 256] + p1[base + tid + 256];
    }
    if (xout) {
        xout[base + tid]       = v0;
        xout[base + tid + 256] = v1;
    }

    float s  = v0 + v1;
    float ss = v0 * v0 + v1 * v1;
    #pragma unroll
    for (int o = 16; o; o >>= 1) {
        s  += __shfl_xor_sync(0xffffffffu, s,  o);
        ss += __shfl_xor_sync(0xffffffffu, ss, o);
    }
    __shared__ float ws[8], wss[8];
    int w = tid >> 5, ln = tid & 31;
    if (ln == 0) { ws[w] = s; wss[w] = ss; }
    __syncthreads();
    __shared__ float s_mu, s_rstd;
    if (tid == 0) {
        float S = 0.f, SS = 0.f;
        #pragma unroll
        for (int i = 0; i < 8; i++) { S += ws[i]; SS += wss[i]; }
        float mu  = S * (1.0f / DIM);
        float var = SS * (1.0f / DIM) - mu * mu;
        s_mu = mu; s_rstd = rsqrtf(var + 1e-5f);
    }
    __syncthreads();
    float mu = s_mu, rstd = s_rstd;
    float o0 = (v0 - mu) * rstd * g[tid]       + b[tid];
    float o1 = (v1 - mu) * rstd * g[tid + 256] + b[tid + 256];
    if (y) {
        y[base + tid]       = o0;
        y[base + tid + 256] = o1;
    }
    if (yh) {
        __nv_bfloat16 h0, l0, h1, l1;
        split_bf16(o0, h0, l0);
        split_bf16(o1, h1, l1);
        yh[base + tid]       = h0;
        yh[base + tid + 256] = h1;
        yl[base + tid]       = l0;
        yl[base + tid + 256] = l1;
    }
}

// ---------------- FA2-style mma attention (online softmax, 2 CTAs/SM) ---------
#define QT    64
#define TSTR  72
#define TILE_B (64*TSTR*2)     // 9216

// smem byte offsets
#define A4_QH   0
#define A4_QL   9216
#define A4_K    18432          // 2 bufs x (hi,lo) = 36864
#define A4_V    55296          // 36864
#define A4_P    92160          // hi,lo = 18432
#define A4_RED  110592         // redmax[128] + redsum[128] floats = 1024
#define A4_BYTES 111616

__global__ void __launch_bounds__(256, 2)
attn_kernel(const __nv_bfloat16* __restrict__ qh, const __nv_bfloat16* __restrict__ ql,
            const __nv_bfloat16* __restrict__ kh, const __nv_bfloat16* __restrict__ kl,
            const __nv_bfloat16* __restrict__ vth, const __nv_bfloat16* __restrict__ vtl,
            __nv_bfloat16* __restrict__ oh, __nv_bfloat16* __restrict__ ol)
{
    extern __shared__ char sm[];
    __nv_bfloat16* PH = (__nv_bfloat16*)(sm + A4_P);
    __nv_bfloat16* PL = (__nv_bfloat16*)(sm + A4_P + TILE_B);
    float* redmax = (float*)(sm + A4_RED);          // [2][64]
    float* redsum = (float*)(sm + A4_RED + 512);    // [2][64]

    uint32_t sb0 = smem_u32(sm);
    uint32_t uQH = sb0 + A4_QH;
    uint32_t uQL = sb0 + A4_QL;
    uint32_t uK  = sb0 + A4_K;
    uint32_t uV  = sb0 + A4_V;
    uint32_t uPH = sb0 + A4_P;
    uint32_t uPL = uPH + TILE_B;

    int tid  = threadIdx.x;
    int wid  = tid >> 5, lane = tid & 31;
    int mw   = (wid & 3) * 16;       // query rows
    int nw   = (wid >> 2) * 32;      // key cols / d cols
    int grp  = wid >> 2;             // 0 or 1

    int t0  = blockIdx.x * QT;
    int bh  = blockIdx.y;
    int b   = bh >> 3;
    int h   = bh & 7;
    int jbase = t0 - 256;

    // first non-fully-masked K-tile: tile s fully masked iff jbase+64s+63 < 0
    int s0 = (jbase < 0) ? ((-jbase) >> 6) : 0;   // t0=0->4, 64->3, 128->2, 192->1
    if (s0 > 4) s0 = 4;

    int a_row  = mw + (lane & 15);
    int a_koff = (lane >> 4) * 8;
    int b_row  = nw + (lane & 7) + ((lane >> 4) & 1) * 8;
    int b_koff = ((lane >> 3) & 1) * 8;

    // Q load (shares commit group with kv(s0))
    {
        #pragma unroll
        for (int it = 0; it < 4; it++) {
            int vi  = tid + 256 * it;
            int row = vi >> 4, c = vi & 15;
            const __nv_bfloat16* src = (c < 8 ? qh : ql)
                + (size_t)(b * SEQ + t0 + row) * DIM + h * DH + (c & 7) * 8;
            uint32_t dst = (c < 8 ? uQH : uQL) + row * (TSTR * 2) + (c & 7) * 16;
            cpa16(dst, src);
        }
    }

    auto load_kv = [&](int s) {
        int kb = jbase + s * 64;
        uint32_t kbuf = uK + (s & 1) * (2 * TILE_B);
        uint32_t vbuf = uV + (s & 1) * (2 * TILE_B);
        #pragma unroll
        for (int it = 0; it < 4; it++) {
            int vi  = tid + 256 * it;
            int row = vi >> 4, c = vi & 15;
            int j = kb + row;
            int jc = j < 0 ? 0 : j;
            const __nv_bfloat16* src = (c < 8 ? kh : kl)
                + (size_t)(b * SEQ + jc) * DIM + h * DH + (c & 7) * 8;
            uint32_t dst = kbuf + (c < 8 ? 0 : TILE_B) + row * (TSTR * 2) + (c & 7) * 16;
            cpa16(dst, src);
        }
        #pragma unroll
        for (int it = 0; it < 4; it++) {
            int vi  = tid + 256 * it;
            int row = vi >> 4, c = vi & 15;       // row = d (0..63)
            int j0 = kb + (c & 7) * 8;
            int jc = j0 < 0 ? 0 : j0;
            const __nv_bfloat16* src = (c < 8 ? vth : vtl)
                + (size_t)(b * DIM + h * DH + row) * SEQ + jc;
            uint32_t dst = vbuf + (c < 8 ? 0 : TILE_B) + row * (TSTR * 2) + (c & 7) * 16;
            cpa16(dst, src);
        }
        asm volatile("cp.async.commit_group;" ::: "memory");
    };

    load_kv(s0);
    if (s0 + 1 < 5) load_kv(s0 + 1);

    float o[4][4];
    #pragma unroll
    for (int i = 0; i < 4; i++)
        #pragma unroll
        for (int j = 0; j < 4; j++) o[i][j] = 0.f;
    float m[2] = {-1e30f, -1e30f};
    float l[2] = {0.f, 0.f};

    int r0 = mw + (lane >> 2);   // half-0 row; half-1 row = r0+8

    for (int s = s0; s < 5; s++) {
        if (s < 4) asm volatile("cp.async.wait_group 1;" ::: "memory");
        else       asm volatile("cp.async.wait_group 0;" ::: "memory");
        __syncthreads();

        uint32_t sKH = uK + (s & 1) * (2 * TILE_B);
        uint32_t sKL = sKH + TILE_B;
        int kb = jbase + s * 64;

        // ---- QK^T ----
        float acc[4][4];
        #pragma unroll
        for (int i = 0; i < 4; i++)
            #pragma unroll
            for (int j = 0; j < 4; j++) acc[i][j] = 0.f;

        #pragma unroll
        for (int k16 = 0; k16 < 4; k16++) {
            int kk0 = k16 * 16;
            uint32_t ah[4], al[4];
            uint32_t aoff = (a_row * TSTR + kk0 + a_koff) * 2;
            ldmx4(ah, uQH + aoff);
            ldmx4(al, uQL + aoff);
            #pragma unroll
            for (int ng = 0; ng < 2; ng++) {
                uint32_t bh2[4], bl2[4];
                uint32_t boff = ((b_row + ng * 16) * TSTR + kk0 + b_koff) * 2;
                ldmx4(bh2, sKH + boff);
                ldmx4(bl2, sKL + boff);
                mma_bf16(acc[2*ng],   ah, bh2);
                mma_bf16(acc[2*ng],   ah, bl2);
                mma_bf16(acc[2*ng],   al, bh2);
                mma_bf16(acc[2*ng+1], ah, bh2 + 2);
                mma_bf16(acc[2*ng+1], ah, bl2 + 2);
                mma_bf16(acc[2*ng+1], al, bh2 + 2);
            }
        }

        // ---- mask + tile row max (warp part) ----
        float tmax[2] = {-INFINITY, -INFINITY};
        #pragma unroll
        for (int half = 0; half < 2; half++) {
            int r = r0 + half * 8;
            int ig = t0 + r;
            #pragma unroll
            for (int nt = 0; nt < 4; nt++) {
                #pragma unroll
                for (int e = 0; e < 2; e++) {
                    int jg = kb + nw + nt * 8 + (lane & 3) * 2 + e;
                    bool ok = (jg >= 0) && (jg <= ig) && (ig - jg < WIN);
                    float vv = ok ? acc[nt][half * 2 + e] : -INFINITY;
                    acc[nt][half * 2 + e] = vv;
                    tmax[half] = fmaxf(tmax[half], vv);
                }
            }
            tmax[half] = fmaxf(tmax[half], __shfl_xor_sync(0xffffffffu, tmax[half], 1));
            tmax[half] = fmaxf(tmax[half], __shfl_xor_sync(0xffffffffu, tmax[half], 2));
        }
        if ((lane & 3) == 0) {
            redmax[grp * 64 + r0]     = tmax[0];
            redmax[grp * 64 + r0 + 8] = tmax[1];
        }
        __syncthreads();

        // ---- online update: m, rescale o; compute P; write P; partial sums ----
        float tsum[2] = {0.f, 0.f};
        #pragma unroll
        for (int half = 0; half < 2; half++) {
            int r = r0 + half * 8;
            float tm = fmaxf(redmax[r], redmax[64 + r]);
            float mn = fmaxf(m[half], tm);
            float sc = __expf(m[half] - mn);
            m[half] = mn;
            l[half] *= sc;
            #pragma unroll
            for (int nt = 0; nt < 4; nt++) {
                o[nt][half * 2 + 0] *= sc;
                o[nt][half * 2 + 1] *= sc;
                float p0v = __expf(acc[nt][half * 2 + 0] - mn);
                float p1v = __expf(acc[nt][half * 2 + 1] - mn);
                tsum[half] += p0v + p1v;
                __nv_bfloat16 h0, l0b, h1, l1b;
                split_bf16(p0v, h0, l0b);
                split_bf16(p1v, h1, l1b);
                __nv_bfloat162 hh; hh.x = h0; hh.y = h1;
                __nv_bfloat162 ll; ll.x = l0b; ll.y = l1b;
                int off = r * TSTR + nw + nt * 8 + (lane & 3) * 2;
                *reinterpret_cast<__nv_bfloat162*>(PH + off) = hh;
                *reinterpret_cast<__nv_bfloat162*>(PL + off) = ll;
            }
            tsum[half] += __shfl_xor_sync(0xffffffffu, tsum[half], 1);
            tsum[half] += __shfl_xor_sync(0xffffffffu, tsum[half], 2);
        }
        if ((lane & 3) == 0) {
            redsum[grp * 64 + r0]     = tsum[0];
            redsum[grp * 64 + r0 + 8] = tsum[1];
        }
        __syncthreads();   // P visible + sums visible

        l[0] += redsum[r0]     + redsum[64 + r0];
        l[1] += redsum[r0 + 8] + redsum[64 + r0 + 8];

        // ---- PV ----
        uint32_t sVH = uV + (s & 1) * (2 * TILE_B);
        uint32_t sVL = sVH + TILE_B;
        #pragma unroll
        for (int k16 = 0; k16 < 4; k16++) {
            int kk0 = k16 * 16;
            uint32_t ah[4], al[4];
            uint32_t aoff = (a_row * TSTR + kk0 + a_koff) * 2;
            ldmx4(ah, uPH + aoff);
            ldmx4(al, uPL + aoff);
            #pragma unroll
            for (int ng = 0; ng < 2; ng++) {
                uint32_t bh2[4], bl2[4];
                uint32_t boff = ((b_row + ng * 16) * TSTR + kk0 + b_koff) * 2;
                ldmx4(bh2, sVH + boff);
                ldmx4(bl2, sVL + boff);
                mma_bf16(o[2*ng],   ah, bh2);
                mma_bf16(o[2*ng],   ah, bl2);
                mma_bf16(o[2*ng],   al, bh2);
                mma_bf16(o[2*ng+1], ah, bh2 + 2);
                mma_bf16(o[2*ng+1], ah, bl2 + 2);
                mma_bf16(o[2*ng+1], al, bh2 + 2);
            }
        }
        __syncthreads();   // K/V bufs + P free for reuse
        if (s + 2 < 5) load_kv(s + 2);
    }

    // ---- write out ----
    float li[2] = {1.0f / l[0], 1.0f / l[1]};
    #pragma unroll
    for (int nt = 0; nt < 4; nt++) {
        #pragma unroll
        for (int half = 0; half < 2; half++) {
            int r = r0 + half * 8;
            int d = nw + nt * 8 + (lane & 3) * 2;
            float v0 = o[nt][half * 2 + 0] * li[half];
            float v1 = o[nt][half * 2 + 1] * li[half];
            __nv_bfloat16 h0, l0b, h1, l1b;
            split_bf16(v0, h0, l0b);
            split_bf16(v1, h1, l1b);
            size_t base = (size_t)(b * SEQ + t0 + r) * DIM + h * DH + d;
            __nv_bfloat162 hh; hh.x = h0; hh.y = h1;
            __nv_bfloat162 ll; ll.x = l0b; ll.y = l1b;
            *reinterpret_cast<__nv_bfloat162*>(oh + base) = hh;
            *reinterpret_cast<__nv_bfloat162*>(ol + base) = ll;
        }
    }
}

// ---------------- host launcher ----------------------------------------------
extern "C" void kernel_launch(void* const* d_in, const int* in_sizes, int n_in,
                              void* d_out, int out_size)
{
    const float* tokens = (const float*)d_in[0];
    const float* Wq = (const float*)d_in[1];
    const float* Wk = (const float*)d_in[2];
    const float* Wv = (const float*)d_in[3];
    const float* Wo = (const float*)d_in[4];
    const float* bq = (const float*)d_in[5];
    const float* bk = (const float*)d_in[6];
    const float* bv = (const float*)d_in[7];
    const float* bo = (const float*)d_in[8];
    const float* W1 = (const float*)d_in[9];
    const float* b1 = (const float*)d_in[10];
    const float* W2 = (const float*)d_in[11];
    const float* b2 = (const float*)d_in[12];
    const float* g1 = (const float*)d_in[13];
    const float* be1= (const float*)d_in[14];
    const float* g2 = (const float*)d_in[15];
    const float* be2= (const float*)d_in[16];
    const float* gf = (const float*)d_in[17];
    const float* bf = (const float*)d_in[18];

    float *x, *q, *k, *v;
    cudaGetSymbolAddress((void**)&x, g_x);
    cudaGetSymbolAddress((void**)&q, g_q);
    cudaGetSymbolAddress((void**)&k, g_k);
    cudaGetSymbolAddress((void**)&v, g_v);
    float* p0 = q;
    float* p1 = k;

    __nv_bfloat16 *xnh, *xnl, *atth, *attl, *hbh, *hbl;
    cudaGetSymbolAddress((void**)&xnh,  g_xnh);
    cudaGetSymbolAddress((void**)&xnl,  g_xnl);
    cudaGetSymbolAddress((void**)&atth, g_atth);
    cudaGetSymbolAddress((void**)&attl, g_attl);
    cudaGetSymbolAddress((void**)&hbh,  g_hbh);
    cudaGetSymbolAddress((void**)&hbl,  g_hbl);

    __nv_bfloat16 *qh, *ql, *kh, *kl, *vth, *vtl;
    cudaGetSymbolAddress((void**)&qh,  g_qh);
    cudaGetSymbolAddress((void**)&ql,  g_ql);
    cudaGetSymbolAddress((void**)&kh,  g_kh);
    cudaGetSymbolAddress((void**)&kl,  g_kl);
    cudaGetSymbolAddress((void**)&vth, g_vth);
    cudaGetSymbolAddress((void**)&vtl, g_vtl);

    __nv_bfloat16 *wqh,*wql,*wkh,*wkl,*wvh,*wvl,*woh,*wol,*w1h,*w1l,*w2h,*w2l;
    cudaGetSymbolAddress((void**)&wqh, g_wqt_h); cudaGetSymbolAddress((void**)&wql, g_wqt_l);
    cudaGetSymbolAddress((void**)&wkh, g_wkt_h); cudaGetSymbolAddress((void**)&wkl, g_wkt_l);
    cudaGetSymbolAddress((void**)&wvh, g_wvt_h); cudaGetSymbolAddress((void**)&wvl, g_wvt_l);
    cudaGetSymbolAddress((void**)&woh, g_wot_h); cudaGetSymbolAddress((void**)&wol, g_wot_l);
    cudaGetSymbolAddress((void**)&w1h, g_w1t_h); cudaGetSymbolAddress((void**)&w1l, g_w1t_l);
    cudaGetSymbolAddress((void**)&w2h, g_w2t_h); cudaGetSymbolAddress((void**)&w2l, g_w2t_l);

    cudaFuncSetAttribute(attn_kernel, cudaFuncAttributeMaxDynamicSharedMemorySize,
                         A4_BYTES);
    cudaFuncSetAttribute(qkv_mm, cudaFuncAttributeMaxDynamicSharedMemorySize, DSM_BYTES);
    cudaFuncSetAttribute(gemm_ksplit, cudaFuncAttributeMaxDynamicSharedMemorySize, DSM_BYTES);
    cudaFuncSetAttribute(gemm_mm<1,0,0,1>, cudaFuncAttributeMaxDynamicSharedMemorySize, DSM_BYTES);

    cudaMemcpyAsync(x, tokens, sizeof(float) * (size_t)BT * DIM,
                    cudaMemcpyDeviceToDevice, 0);

    // weight conversion
    {
        dim3 blk(32, 8);
        dim3 gdd(DIM / 32, DIM / 32, NL);
        wconv_kernel<<<gdd, blk>>>(Wq, wqh, wql, DIM, DIM);
        wconv_kernel<<<gdd, blk>>>(Wk, wkh, wkl, DIM, DIM);
        wconv_kernel<<<gdd, blk>>>(Wv, wvh, wvl, DIM, DIM);
        wconv_kernel<<<gdd, blk>>>(Wo, woh, wol, DIM, DIM);
        dim3 g1d(DFF / 32, DIM / 32, NL);
        wconv_kernel<<<g1d, blk>>>(W1, w1h, w1l, DIM, DFF);
        dim3 g2d(DIM / 32, DFF / 32, NL);
        wconv_kernel<<<g2d, blk>>>(W2, w2h, w2l, DFF, DIM);
    }

    dim3 gQKV(DIM / 128, BT / 128, 3);
    dim3 gKS (DIM / 128, BT / 128, 2);
    dim3 gF  (DFF / 128, BT / 128);
    dim3 gAtt(SEQ / QT, BATCH * NH);

    for (int l = 0; l < NL; l++) {
        size_t wofs  = (size_t)l * DIM * DIM;
        size_t w1ofs = (size_t)l * DIM * DFF;

        const float* pp0 = (l == 0) ? nullptr : p0;
        const float* pp1 = (l == 0) ? nullptr : p1;
        float* xo = (l == 0) ? nullptr : x;
        ln_kernel<<<BT, 256>>>(x, pp0, pp1, g1 + l * DIM, be1 + l * DIM,
                               xo, nullptr, xnh, xnl);

        qkv_mm<<<gQKV, 256, DSM_BYTES>>>(xnh, xnl,
                                         wqh + wofs, wql + wofs,
                                         wkh + wofs, wkl + wofs,
                                         wvh + wofs, wvl + wofs,
                                         bq + l * DIM, bk + l * DIM, bv + l * DIM,
                                         q, k, v);

        qkvprep_kernel<<<PREP_BLOCKS, 256>>>(q, k, v, qh, ql, kh, kl, vth, vtl);

        attn_kernel<<<gAtt, 256, A4_BYTES>>>(qh, ql, kh, kl, vth, vtl, atth, attl);

        gemm_ksplit<<<gKS, 256, DSM_BYTES>>>(atth, attl, woh + wofs, wol + wofs,
                                             bo + l * DIM, p0, p1, DIM, DIM);

        ln_kernel<<<BT, 256>>>(x, p0, p1, g2 + l * DIM, be2 + l * DIM,
                               x, nullptr, xnh, xnl);

        gemm_mm<1,0,0,1><<<gF, 256, DSM_BYTES>>>(xnh, xnl, w1h + w1ofs, w1l + w1ofs,
                                                 b1 + l * DFF, nullptr, nullptr, hbh, hbl,
                                                 DFF, DIM);

        gemm_ksplit<<<gKS, 256, DSM_BYTES>>>(hbh, hbl, w2h + w1ofs, w2l + w1ofs,
                                             b2 + l * DIM, p0, p1, DIM, DFF);
    }

    ln_kernel<<<BT, 256>>>(x, p0, p1, gf, bf, nullptr, (float*)d_out,
                           nullptr, nullptr);
}

// round 17
// speedup vs baseline: 1.0868x; 1.0125x over previous
#include <cuda_runtime.h>
#include <cuda_bf16.h>
#include <math.h>
#include <stdint.h>

#define BATCH 2
#define SEQ   2048
#define DIM   512
#define NH    8
#define DH    64
#define NL    4
#define DFF   2048
#define WIN   256
#define BT    (BATCH*SEQ)   // 4096

// ---------------- scratch (static device globals; no allocation) -------------
__device__ float g_x [BT*DIM];
__device__ float g_q [BT*DIM];    // q ; later Wo/W2 split-K partial 0
__device__ float g_k [BT*DIM];    // k ; later Wo/W2 split-K partial 1

__device__ __nv_bfloat16 g_xnh [BT*DIM];
__device__ __nv_bfloat16 g_xnl [BT*DIM];
__device__ __nv_bfloat16 g_atth[BT*DIM];
__device__ __nv_bfloat16 g_attl[BT*DIM];
__device__ __nv_bfloat16 g_hbh [BT*DFF];
__device__ __nv_bfloat16 g_hbl [BT*DFF];

// attention operands (pre-split); V stays [t][d] row-major
__device__ __nv_bfloat16 g_qh [BT*DIM], g_ql [BT*DIM];
__device__ __nv_bfloat16 g_kh [BT*DIM], g_kl [BT*DIM];
__device__ __nv_bfloat16 g_vh [BT*DIM], g_vl [BT*DIM];

// transposed split weights: [L][N][K]
__device__ __nv_bfloat16 g_wqt_h[NL*DIM*DIM],  g_wqt_l[NL*DIM*DIM];
__device__ __nv_bfloat16 g_wkt_h[NL*DIM*DIM],  g_wkt_l[NL*DIM*DIM];
__device__ __nv_bfloat16 g_wvt_h[NL*DIM*DIM],  g_wvt_l[NL*DIM*DIM];
__device__ __nv_bfloat16 g_wot_h[NL*DIM*DIM],  g_wot_l[NL*DIM*DIM];
__device__ __nv_bfloat16 g_w1t_h[NL*DIM*DFF],  g_w1t_l[NL*DIM*DFF];
__device__ __nv_bfloat16 g_w2t_h[NL*DFF*DIM],  g_w2t_l[NL*DFF*DIM];

// ---------------- PTX helpers --------------------------------------------------
__device__ __forceinline__ uint32_t smem_u32(const void* p) {
    uint32_t a;
    asm("{ .reg .u64 t; cvta.to.shared.u64 t, %1; cvt.u32.u64 %0, t; }"
        : "=r"(a) : "l"(p));
    return a;
}

__device__ __forceinline__ void cpa16(uint32_t dst, const void* src)
{
    asm volatile("cp.async.cg.shared.global [%0], [%1], 16;" :: "r"(dst), "l"(src));
}

__device__ __forceinline__ void ldmx4(uint32_t* r, uint32_t addr)
{
    asm volatile("ldmatrix.sync.aligned.m8n8.x4.shared.b16 {%0,%1,%2,%3}, [%4];"
        : "=r"(r[0]), "=r"(r[1]), "=r"(r[2]), "=r"(r[3]) : "r"(addr));
}

__device__ __forceinline__ void ldmx4t(uint32_t* r, uint32_t addr)
{
    asm volatile("ldmatrix.sync.aligned.m8n8.x4.trans.shared.b16 {%0,%1,%2,%3}, [%4];"
        : "=r"(r[0]), "=r"(r[1]), "=r"(r[2]), "=r"(r[3]) : "r"(addr));
}

__device__ __forceinline__ void mma_bf16(float* c, const uint32_t* a, const uint32_t* b)
{
    asm volatile(
        "mma.sync.aligned.m16n8k16.row.col.f32.bf16.bf16.f32 "
        "{%0,%1,%2,%3}, {%4,%5,%6,%7}, {%8,%9}, {%0,%1,%2,%3};"
        : "+f"(c[0]), "+f"(c[1]), "+f"(c[2]), "+f"(c[3])
        : "r"(a[0]), "r"(a[1]), "r"(a[2]), "r"(a[3]), "r"(b[0]), "r"(b[1]));
}

__device__ __forceinline__ void split_bf16(float v, __nv_bfloat16& h, __nv_bfloat16& l)
{
    h = __float2bfloat16(v);
    l = __float2bfloat16(v - __bfloat162float(h));
}

// ---------------- mma.sync bf16-split GEMM (2-stage, 2 CTAs/SM) ----------------
#define TKC       32
#define RSTR      40
#define ARR_BYTES (128*RSTR*2)
#define STG_BYTES (4*ARR_BYTES)       // 40960
#define DSM_BYTES (2*STG_BYTES)       // 81920 -> 2 CTAs/SM

template <int GELU, int RES, int OUTF32, int OUTBF>
__device__ __forceinline__ void gemm_mm_core(
    const __nv_bfloat16* __restrict__ Ah, const __nv_bfloat16* __restrict__ Al,
    const __nv_bfloat16* __restrict__ Bh, const __nv_bfloat16* __restrict__ Bl,
    const float* __restrict__ bias, const float* __restrict__ res,
    float* __restrict__ C, __nv_bfloat16* __restrict__ Oh, __nv_bfloat16* __restrict__ Ol,
    int N, int Kstr, int kbase, int Kloop, int m0, int n0)
{
    extern __shared__ char dsm[];
    uint32_t sm0 = smem_u32(dsm);

    int tid  = threadIdx.x;
    int wid  = tid >> 5, lane = tid & 31;
    int mw   = (wid & 3) * 32;
    int nw   = (wid >> 2) * 64;

    float acc[2][8][4];
    #pragma unroll
    for (int i = 0; i < 2; i++)
        #pragma unroll
        for (int j = 0; j < 8; j++)
            #pragma unroll
            for (int t = 0; t < 4; t++) acc[i][j][t] = 0.f;

    int nk = Kloop / TKC;

    auto load_stage = [&](int c) {
        uint32_t sb = sm0 + (c & 1) * STG_BYTES;
        int k0 = kbase + c * TKC;
        #pragma unroll
        for (int it = 0; it < 8; it++) {
            int idx  = it * 256 + tid;
            int arr  = idx >> 9;
            int rem  = idx & 511;
            int row  = rem >> 2;
            int part = rem & 3;
            uint32_t dst = sb + arr * ARR_BYTES + row * (RSTR * 2) + part * 16;
            const __nv_bfloat16* src;
            if      (arr == 0) src = Ah + (size_t)(m0 + row) * Kstr + k0 + part * 8;
            else if (arr == 1) src = Al + (size_t)(m0 + row) * Kstr + k0 + part * 8;
            else if (arr == 2) src = Bh + (size_t)(n0 + row) * Kstr + k0 + part * 8;
            else               src = Bl + (size_t)(n0 + row) * Kstr + k0 + part * 8;
            cpa16(dst, src);
        }
        asm volatile("cp.async.commit_group;" ::: "memory");
    };

    load_stage(0);

    int a_row = mw + (lane & 15);
    int a_koff = (lane >> 4) * 8;
    int b_row = nw + (lane & 7) + ((lane >> 4) & 1) * 8;
    int b_koff = ((lane >> 3) & 1) * 8;

    for (int c = 0; c < nk; c++) {
        asm volatile("cp.async.wait_group 0;" ::: "memory");
        __syncthreads();

        if (c + 1 < nk) load_stage(c + 1);

        uint32_t sb  = sm0 + (c & 1) * STG_BYTES;
        uint32_t sah = sb;
        uint32_t sal = sb + ARR_BYTES;
        uint32_t sbh = sb + 2 * ARR_BYTES;
        uint32_t sbl = sb + 3 * ARR_BYTES;

        #pragma unroll
        for (int h = 0; h < 2; h++) {
            int k0 = h * 16;
            uint32_t ah[2][4], al[2][4];
            #pragma unroll
            for (int mt = 0; mt < 2; mt++) {
                uint32_t off = ((a_row + mt * 16) * RSTR + k0 + a_koff) * 2;
                ldmx4(ah[mt], sah + off);
                ldmx4(al[mt], sal + off);
            }
            #pragma unroll
            for (int ng = 0; ng < 4; ng++) {
                uint32_t bh[4], bl[4];
                uint32_t off = ((b_row + ng * 16) * RSTR + k0 + b_koff) * 2;
                ldmx4(bh, sbh + off);
                ldmx4(bl, sbl + off);
                #pragma unroll
                for (int mt = 0; mt < 2; mt++) {
                    mma_bf16(acc[mt][2*ng],   ah[mt], bh);
                    mma_bf16(acc[mt][2*ng],   ah[mt], bl);
                    mma_bf16(acc[mt][2*ng],   al[mt], bh);
                    mma_bf16(acc[mt][2*ng+1], ah[mt], bh + 2);
                    mma_bf16(acc[mt][2*ng+1], ah[mt], bl + 2);
                    mma_bf16(acc[mt][2*ng+1], al[mt], bh + 2);
                }
            }
        }
        __syncthreads();
    }

    int cbase_n = n0 + nw + (lane & 3) * 2;
    #pragma unroll
    for (int mt = 0; mt < 2; mt++) {
        #pragma unroll
        for (int half = 0; half < 2; half++) {
            int row = m0 + mw + mt * 16 + (lane >> 2) + half * 8;
            size_t rbase = (size_t)row * N;
            #pragma unroll
            for (int nt = 0; nt < 8; nt++) {
                int col = cbase_n + nt * 8;
                float v0 = acc[mt][nt][half * 2 + 0];
                float v1 = acc[mt][nt][half * 2 + 1];
                if (bias) {
                    float2 b2 = *reinterpret_cast<const float2*>(bias + col);
                    v0 += b2.x; v1 += b2.y;
                }
                if (GELU) {
                    v0 = 0.5f * v0 * (1.0f + erff(v0 * 0.70710678118654752f));
                    v1 = 0.5f * v1 * (1.0f + erff(v1 * 0.70710678118654752f));
                }
                if (RES) {
                    float2 r2 = *reinterpret_cast<const float2*>(res + rbase + col);
                    v0 += r2.x; v1 += r2.y;
                }
                if (OUTF32) {
                    *reinterpret_cast<float2*>(C + rbase + col) = make_float2(v0, v1);
                }
                if (OUTBF) {
                    __nv_bfloat16 h0, l0, h1, l1;
                    split_bf16(v0, h0, l0);
                    split_bf16(v1, h1, l1);
                    __nv_bfloat162 hh; hh.x = h0; hh.y = h1;
                    __nv_bfloat162 ll; ll.x = l0; ll.y = l1;
                    *reinterpret_cast<__nv_bfloat162*>(Oh + rbase + col) = hh;
                    *reinterpret_cast<__nv_bfloat162*>(Ol + rbase + col) = ll;
                }
            }
        }
    }
}

// plain GEMM (full K)
template <int GELU, int RES, int OUTF32, int OUTBF>
__global__ void __launch_bounds__(256, 2)
gemm_mm(const __nv_bfloat16* __restrict__ Ah, const __nv_bfloat16* __restrict__ Al,
        const __nv_bfloat16* __restrict__ Bh, const __nv_bfloat16* __restrict__ Bl,
        const float* __restrict__ bias, const float* __restrict__ res,
        float* __restrict__ C, __nv_bfloat16* __restrict__ Oh,
        __nv_bfloat16* __restrict__ Ol, int N, int K)
{
    gemm_mm_core<GELU, RES, OUTF32, OUTBF>(Ah, Al, Bh, Bl, bias, res, C, Oh, Ol,
                                           N, K, 0, K, blockIdx.y * 128, blockIdx.x * 128);
}

// split-K=2 GEMM: grid.z selects k-half; writes fp32 partial (bias only in half 0)
__global__ void __launch_bounds__(256, 2)
gemm_ksplit(const __nv_bfloat16* __restrict__ Ah, const __nv_bfloat16* __restrict__ Al,
            const __nv_bfloat16* __restrict__ Bh, const __nv_bfloat16* __restrict__ Bl,
            const float* __restrict__ bias,
            float* __restrict__ p0, float* __restrict__ p1, int N, int K)
{
    int kz = blockIdx.z;
    float* C = kz ? p1 : p0;
    const float* bi = kz ? nullptr : bias;
    gemm_mm_core<0, 0, 1, 0>(Ah, Al, Bh, Bl, bi, nullptr, C, nullptr, nullptr,
                             N, K, kz * (K / 2), K / 2,
                             blockIdx.y * 128, blockIdx.x * 128);
}

// fused QKV (full K): z=0 -> q (f32), z=1 -> k (f32), z=2 -> v (bf16 hi/lo [t][d])
__global__ void __launch_bounds__(256, 2)
qkv_mm(const __nv_bfloat16* __restrict__ Ah, const __nv_bfloat16* __restrict__ Al,
       const __nv_bfloat16* __restrict__ Bqh, const __nv_bfloat16* __restrict__ Bql,
       const __nv_bfloat16* __restrict__ Bkh, const __nv_bfloat16* __restrict__ Bkl,
       const __nv_bfloat16* __restrict__ Bvh, const __nv_bfloat16* __restrict__ Bvl,
       const float* __restrict__ bq, const float* __restrict__ bk,
       const float* __restrict__ bv,
       float* __restrict__ q, float* __restrict__ k,
       __nv_bfloat16* __restrict__ vh, __nv_bfloat16* __restrict__ vl)
{
    int z = blockIdx.z;
    int m0 = blockIdx.y * 128, n0 = blockIdx.x * 128;
    if (z == 0) {
        gemm_mm_core<0,0,1,0>(Ah, Al, Bqh, Bql, bq, nullptr, q, nullptr, nullptr,
                              DIM, DIM, 0, DIM, m0, n0);
    } else if (z == 1) {
        gemm_mm_core<0,0,1,0>(Ah, Al, Bkh, Bkl, bk, nullptr, k, nullptr, nullptr,
                              DIM, DIM, 0, DIM, m0, n0);
    } else {
        gemm_mm_core<0,0,0,1>(Ah, Al, Bvh, Bvl, bv, nullptr, nullptr, vh, vl,
                              DIM, DIM, 0, DIM, m0, n0);
    }
}

// ---------------- weight transpose + bf16 split -------------------------------
__global__ void wconv_kernel(const float* __restrict__ W,
                             __nv_bfloat16* __restrict__ hiT,
                             __nv_bfloat16* __restrict__ loT, int K, int N)
{
    __shared__ float t[32][33];
    int n0 = blockIdx.x * 32, k0 = blockIdx.y * 32;
    size_t lofs = (size_t)blockIdx.z * K * N;
    const float* Wl = W + lofs;
    int tx = threadIdx.x, ty = threadIdx.y;
    #pragma unroll
    for (int i = 0; i < 4; i++)
        t[ty + 8 * i][tx] = Wl[(size_t)(k0 + ty + 8 * i) * N + n0 + tx];
    __syncthreads();
    __nv_bfloat16* ho = hiT + lofs;
    __nv_bfloat16* lo = loT + lofs;
    #pragma unroll
    for (int i = 0; i < 4; i++) {
        float v = t[tx][ty + 8 * i];
        __nv_bfloat16 h, l;
        split_bf16(v, h, l);
        ho[(size_t)(n0 + ty + 8 * i) * K + k0 + tx] = h;
        lo[(size_t)(n0 + ty + 8 * i) * K + k0 + tx] = l;
    }
}

// ---------------- qkv prep: RoPE-split (q,k) only ------------------------------
#define PREP_BLOCKS ((BT*NH*32)/256)            // 4096

__global__ void __launch_bounds__(256)
qkvprep_kernel(const float* __restrict__ q, const float* __restrict__ k,
               __nv_bfloat16* __restrict__ qh, __nv_bfloat16* __restrict__ ql,
               __nv_bfloat16* __restrict__ kh, __nv_bfloat16* __restrict__ kl)
{
    int idx = blockIdx.x * 256 + threadIdx.x;   // over BT*NH*32
    int d  = idx & 31;
    int h  = (idx >> 5) & (NH - 1);
    int bt = idx >> 8;
    int t  = bt & (SEQ - 1);

    float inv_freq = __powf(10000.0f, -(float)(2 * d) / (float)DH);
    float ang = (float)t * inv_freq;
    float c, s;
    sincosf(ang, &s, &c);

    size_t base = (size_t)bt * DIM + h * DH + d;

    float q1 = q[base], q2 = q[base + 32];
    float qo1 = (q1 * c - q2 * s) * 0.125f;
    float qo2 = (q2 * c + q1 * s) * 0.125f;
    __nv_bfloat16 hh, ll;
    split_bf16(qo1, hh, ll); qh[base] = hh;      ql[base] = ll;
    split_bf16(qo2, hh, ll); qh[base + 32] = hh; ql[base + 32] = ll;

    float k1 = k[base], k2 = k[base + 32];
    float ko1 = k1 * c - k2 * s;
    float ko2 = k2 * c + k1 * s;
    split_bf16(ko1, hh, ll); kh[base] = hh;      kl[base] = ll;
    split_bf16(ko2, hh, ll); kh[base + 32] = hh; kl[base + 32] = ll;
}

// ---------------- LayerNorm (optionally folds split-K partials) ----------------
__global__ void ln_kernel(const float* __restrict__ x,
                          const float* __restrict__ p0, const float* __restrict__ p1,
                          const float* __restrict__ g, const float* __restrict__ b,
                          float* __restrict__ xout, float* __restrict__ y,
                          __nv_bfloat16* __restrict__ yh, __nv_bfloat16* __restrict__ yl)
{
    int row = blockIdx.x;
    int tid = threadIdx.x;
    size_t base = (size_t)row * DIM;

    float v0 = x[base + tid];
    float v1 = x[base + tid + 256];
    if (p0) {
        v0 += p0[base + tid] + p1[base + tid];
        v1 += p0[base + tid + 256] + p1[base + tid + 256];
    }
    if (xout) {
        xout[base + tid]       = v0;
        xout[base + tid + 256] = v1;
    }

    float s  = v0 + v1;
    float ss = v0 * v0 + v1 * v1;
    #pragma unroll
    for (int o = 16; o; o >>= 1) {
        s  += __shfl_xor_sync(0xffffffffu, s,  o);
        ss += __shfl_xor_sync(0xffffffffu, ss, o);
    }
    __shared__ float ws[8], wss[8];
    int w = tid >> 5, ln = tid & 31;
    if (ln == 0) { ws[w] = s; wss[w] = ss; }
    __syncthreads();
    __shared__ float s_mu, s_rstd;
    if (tid == 0) {
        float S = 0.f, SS = 0.f;
        #pragma unroll
        for (int i = 0; i < 8; i++) { S += ws[i]; SS += wss[i]; }
        float mu  = S * (1.0f / DIM);
        float var = SS * (1.0f / DIM) - mu * mu;
        s_mu = mu; s_rstd = rsqrtf(var + 1e-5f);
    }
    __syncthreads();
    float mu = s_mu, rstd = s_rstd;
    float o0 = (v0 - mu) * rstd * g[tid]       + b[tid];
    float o1 = (v1 - mu) * rstd * g[tid + 256] + b[tid + 256];
    if (y) {
        y[base + tid]       = o0;
        y[base + tid + 256] = o1;
    }
    if (yh) {
        __nv_bfloat16 h0, l0, h1, l1;
        split_bf16(o0, h0, l0);
        split_bf16(o1, h1, l1);
        yh[base + tid]       = h0;
        yh[base + tid + 256] = h1;
        yl[base + tid]       = l0;
        yl[base + tid + 256] = l1;
    }
}

// ---------------- FA2-style mma attention (online softmax, 2 CTAs/SM) ---------
#define QT    64
#define TSTR  72
#define TILE_B (64*TSTR*2)     // 9216

// smem byte offsets
#define A4_QH   0
#define A4_QL   9216
#define A4_K    18432          // 2 bufs x (hi,lo) = 36864
#define A4_V    55296          // 36864
#define A4_P    92160          // hi,lo = 18432
#define A4_RED  110592         // redmax[128] + redsum[128] floats = 1024
#define A4_BYTES 111616

__global__ void __launch_bounds__(256, 2)
attn_kernel(const __nv_bfloat16* __restrict__ qh, const __nv_bfloat16* __restrict__ ql,
            const __nv_bfloat16* __restrict__ kh, const __nv_bfloat16* __restrict__ kl,
            const __nv_bfloat16* __restrict__ vh, const __nv_bfloat16* __restrict__ vl,
            __nv_bfloat16* __restrict__ oh, __nv_bfloat16* __restrict__ ol)
{
    extern __shared__ char sm[];
    __nv_bfloat16* PH = (__nv_bfloat16*)(sm + A4_P);
    __nv_bfloat16* PL = (__nv_bfloat16*)(sm + A4_P + TILE_B);
    float* redmax = (float*)(sm + A4_RED);          // [2][64]
    float* redsum = (float*)(sm + A4_RED + 512);    // [2][64]

    uint32_t sb0 = smem_u32(sm);
    uint32_t uQH = sb0 + A4_QH;
    uint32_t uQL = sb0 + A4_QL;
    uint32_t uK  = sb0 + A4_K;
    uint32_t uV  = sb0 + A4_V;
    uint32_t uPH = sb0 + A4_P;
    uint32_t uPL = uPH + TILE_B;

    int tid  = threadIdx.x;
    int wid  = tid >> 5, lane = tid & 31;
    int mw   = (wid & 3) * 16;       // query rows
    int nw   = (wid >> 2) * 32;      // key cols / d cols
    int grp  = wid >> 2;             // 0 or 1

    int t0  = blockIdx.x * QT;
    int bh  = blockIdx.y;
    int b   = bh >> 3;
    int h   = bh & 7;
    int jbase = t0 - 256;

    // first non-fully-masked K-tile
    int s0 = (jbase < 0) ? ((-jbase) >> 6) : 0;
    if (s0 > 4) s0 = 4;

    int a_row  = mw + (lane & 15);
    int a_koff = (lane >> 4) * 8;
    int b_row  = nw + (lane & 7) + ((lane >> 4) & 1) * 8;
    int b_koff = ((lane >> 3) & 1) * 8;
    // trans-ldmatrix addressing for V [t][d]: row = t, col = d
    int v_row  = (lane & 7) + ((lane >> 3) & 1) * 8;   // t within 16-block
    int v_col  = ((lane >> 4) & 1) * 8;                // d within 16-block

    // Q load (shares commit group with kv(s0))
    {
        #pragma unroll
        for (int it = 0; it < 4; it++) {
            int vi  = tid + 256 * it;
            int row = vi >> 4, c = vi & 15;
            const __nv_bfloat16* src = (c < 8 ? qh : ql)
                + (size_t)(b * SEQ + t0 + row) * DIM + h * DH + (c & 7) * 8;
            uint32_t dst = (c < 8 ? uQH : uQL) + row * (TSTR * 2) + (c & 7) * 16;
            cpa16(dst, src);
        }
    }

    auto load_kv = [&](int s) {
        int kb = jbase + s * 64;
        uint32_t kbuf = uK + (s & 1) * (2 * TILE_B);
        uint32_t vbuf = uV + (s & 1) * (2 * TILE_B);
        #pragma unroll
        for (int it = 0; it < 4; it++) {
            int vi  = tid + 256 * it;
            int row = vi >> 4, c = vi & 15;
            int j = kb + row;
            int jc = j < 0 ? 0 : j;
            const __nv_bfloat16* src = (c < 8 ? kh : kl)
                + (size_t)(b * SEQ + jc) * DIM + h * DH + (c & 7) * 8;
            uint32_t dst = kbuf + (c < 8 ? 0 : TILE_B) + row * (TSTR * 2) + (c & 7) * 16;
            cpa16(dst, src);
        }
        // V tile: same [t][d] addressing as K
        #pragma unroll
        for (int it = 0; it < 4; it++) {
            int vi  = tid + 256 * it;
            int row = vi >> 4, c = vi & 15;
            int j = kb + row;
            int jc = j < 0 ? 0 : j;
            const __nv_bfloat16* src = (c < 8 ? vh : vl)
                + (size_t)(b * SEQ + jc) * DIM + h * DH + (c & 7) * 8;
            uint32_t dst = vbuf + (c < 8 ? 0 : TILE_B) + row * (TSTR * 2) + (c & 7) * 16;
            cpa16(dst, src);
        }
        asm volatile("cp.async.commit_group;" ::: "memory");
    };

    load_kv(s0);
    if (s0 + 1 < 5) load_kv(s0 + 1);

    float o[4][4];
    #pragma unroll
    for (int i = 0; i < 4; i++)
        #pragma unroll
        for (int j = 0; j < 4; j++) o[i][j] = 0.f;
    float m[2] = {-1e30f, -1e30f};
    float l[2] = {0.f, 0.f};

    int r0 = mw + (lane >> 2);

    for (int s = s0; s < 5; s++) {
        if (s < 4) asm volatile("cp.async.wait_group 1;" ::: "memory");
        else       asm volatile("cp.async.wait_group 0;" ::: "memory");
        __syncthreads();

        uint32_t sKH = uK + (s & 1) * (2 * TILE_B);
        uint32_t sKL = sKH + TILE_B;
        int kb = jbase + s * 64;

        // ---- QK^T ----
        float acc[4][4];
        #pragma unroll
        for (int i = 0; i < 4; i++)
            #pragma unroll
            for (int j = 0; j < 4; j++) acc[i][j] = 0.f;

        #pragma unroll
        for (int k16 = 0; k16 < 4; k16++) {
            int kk0 = k16 * 16;
            uint32_t ah[4], al[4];
            uint32_t aoff = (a_row * TSTR + kk0 + a_koff) * 2;
            ldmx4(ah, uQH + aoff);
            ldmx4(al, uQL + aoff);
            #pragma unroll
            for (int ng = 0; ng < 2; ng++) {
                uint32_t bh2[4], bl2[4];
                uint32_t boff = ((b_row + ng * 16) * TSTR + kk0 + b_koff) * 2;
                ldmx4(bh2, sKH + boff);
                ldmx4(bl2, sKL + boff);
                mma_bf16(acc[2*ng],   ah, bh2);
                mma_bf16(acc[2*ng],   ah, bl2);
                mma_bf16(acc[2*ng],   al, bh2);
                mma_bf16(acc[2*ng+1], ah, bh2 + 2);
                mma_bf16(acc[2*ng+1], ah, bl2 + 2);
                mma_bf16(acc[2*ng+1], al, bh2 + 2);
            }
        }

        // ---- mask + tile row max ----
        float tmax[2] = {-INFINITY, -INFINITY};
        #pragma unroll
        for (int half = 0; half < 2; half++) {
            int r = r0 + half * 8;
            int ig = t0 + r;
            #pragma unroll
            for (int nt = 0; nt < 4; nt++) {
                #pragma unroll
                for (int e = 0; e < 2; e++) {
                    int jg = kb + nw + nt * 8 + (lane & 3) * 2 + e;
                    bool ok = (jg >= 0) && (jg <= ig) && (ig - jg < WIN);
                    float vv = ok ? acc[nt][half * 2 + e] : -INFINITY;
                    acc[nt][half * 2 + e] = vv;
                    tmax[half] = fmaxf(tmax[half], vv);
                }
            }
            tmax[half] = fmaxf(tmax[half], __shfl_xor_sync(0xffffffffu, tmax[half], 1));
            tmax[half] = fmaxf(tmax[half], __shfl_xor_sync(0xffffffffu, tmax[half], 2));
        }
        if ((lane & 3) == 0) {
            redmax[grp * 64 + r0]     = tmax[0];
            redmax[grp * 64 + r0 + 8] = tmax[1];
        }
        __syncthreads();

        // ---- online update; P; partial sums ----
        float tsum[2] = {0.f, 0.f};
        #pragma unroll
        for (int half = 0; half < 2; half++) {
            int r = r0 + half * 8;
            float tm = fmaxf(redmax[r], redmax[64 + r]);
            float mn = fmaxf(m[half], tm);
            float sc = __expf(m[half] - mn);
            m[half] = mn;
            l[half] *= sc;
            #pragma unroll
            for (int nt = 0; nt < 4; nt++) {
                o[nt][half * 2 + 0] *= sc;
                o[nt][half * 2 + 1] *= sc;
                float p0v = __expf(acc[nt][half * 2 + 0] - mn);
                float p1v = __expf(acc[nt][half * 2 + 1] - mn);
                tsum[half] += p0v + p1v;
                __nv_bfloat16 h0, l0b, h1, l1b;
                split_bf16(p0v, h0, l0b);
                split_bf16(p1v, h1, l1b);
                __nv_bfloat162 hh; hh.x = h0; hh.y = h1;
                __nv_bfloat162 ll; ll.x = l0b; ll.y = l1b;
                int off = r * TSTR + nw + nt * 8 + (lane & 3) * 2;
                *reinterpret_cast<__nv_bfloat162*>(PH + off) = hh;
                *reinterpret_cast<__nv_bfloat162*>(PL + off) = ll;
            }
            tsum[half] += __shfl_xor_sync(0xffffffffu, tsum[half], 1);
            tsum[half] += __shfl_xor_sync(0xffffffffu, tsum[half], 2);
        }
        if ((lane & 3) == 0) {
            redsum[grp * 64 + r0]     = tsum[0];
            redsum[grp * 64 + r0 + 8] = tsum[1];
        }
        __syncthreads();

        l[0] += redsum[r0]     + redsum[64 + r0];
        l[1] += redsum[r0 + 8] + redsum[64 + r0 + 8];

        // ---- PV (V fragments via trans-ldmatrix from [t][d] tile) ----
        uint32_t sVH = uV + (s & 1) * (2 * TILE_B);
        uint32_t sVL = sVH + TILE_B;
        #pragma unroll
        for (int k16 = 0; k16 < 4; k16++) {
            int kk0 = k16 * 16;
            uint32_t ah[4], al[4];
            uint32_t aoff = (a_row * TSTR + kk0 + a_koff) * 2;
            ldmx4(ah, uPH + aoff);
            ldmx4(al, uPL + aoff);
            #pragma unroll
            for (int ng = 0; ng < 2; ng++) {
                uint32_t bh2[4], bl2[4];
                uint32_t boff = ((kk0 + v_row) * TSTR + nw + ng * 16 + v_col) * 2;
                ldmx4t(bh2, sVH + boff);
                ldmx4t(bl2, sVL + boff);
                mma_bf16(o[2*ng],   ah, bh2);
                mma_bf16(o[2*ng],   ah, bl2);
                mma_bf16(o[2*ng],   al, bh2);
                mma_bf16(o[2*ng+1], ah, bh2 + 2);
                mma_bf16(o[2*ng+1], ah, bl2 + 2);
                mma_bf16(o[2*ng+1], al, bh2 + 2);
            }
        }
        __syncthreads();
        if (s + 2 < 5) load_kv(s + 2);
    }

    // ---- write out ----
    float li[2] = {1.0f / l[0], 1.0f / l[1]};
    #pragma unroll
    for (int nt = 0; nt < 4; nt++) {
        #pragma unroll
        for (int half = 0; half < 2; half++) {
            int r = r0 + half * 8;
            int d = nw + nt * 8 + (lane & 3) * 2;
            float v0 = o[nt][half * 2 + 0] * li[half];
            float v1 = o[nt][half * 2 + 1] * li[half];
            __nv_bfloat16 h0, l0b, h1, l1b;
            split_bf16(v0, h0, l0b);
            split_bf16(v1, h1, l1b);
            size_t base = (size_t)(b * SEQ + t0 + r) * DIM + h * DH + d;
            __nv_bfloat162 hh; hh.x = h0; hh.y = h1;
            __nv_bfloat162 ll; ll.x = l0b; ll.y = l1b;
            *reinterpret_cast<__nv_bfloat162*>(oh + base) = hh;
            *reinterpret_cast<__nv_bfloat162*>(ol + base) = ll;
        }
    }
}

// ---------------- host launcher ----------------------------------------------
extern "C" void kernel_launch(void* const* d_in, const int* in_sizes, int n_in,
                              void* d_out, int out_size)
{
    const float* tokens = (const float*)d_in[0];
    const float* Wq = (const float*)d_in[1];
    const float* Wk = (const float*)d_in[2];
    const float* Wv = (const float*)d_in[3];
    const float* Wo = (const float*)d_in[4];
    const float* bq = (const float*)d_in[5];
    const float* bk = (const float*)d_in[6];
    const float* bv = (const float*)d_in[7];
    const float* bo = (const float*)d_in[8];
    const float* W1 = (const float*)d_in[9];
    const float* b1 = (const float*)d_in[10];
    const float* W2 = (const float*)d_in[11];
    const float* b2 = (const float*)d_in[12];
    const float* g1 = (const float*)d_in[13];
    const float* be1= (const float*)d_in[14];
    const float* g2 = (const float*)d_in[15];
    const float* be2= (const float*)d_in[16];
    const float* gf = (const float*)d_in[17];
    const float* bf = (const float*)d_in[18];

    float *x, *q, *k;
    cudaGetSymbolAddress((void**)&x, g_x);
    cudaGetSymbolAddress((void**)&q, g_q);
    cudaGetSymbolAddress((void**)&k, g_k);
    float* p0 = q;
    float* p1 = k;

    __nv_bfloat16 *xnh, *xnl, *atth, *attl, *hbh, *hbl;
    cudaGetSymbolAddress((void**)&xnh,  g_xnh);
    cudaGetSymbolAddress((void**)&xnl,  g_xnl);
    cudaGetSymbolAddress((void**)&atth, g_atth);
    cudaGetSymbolAddress((void**)&attl, g_attl);
    cudaGetSymbolAddress((void**)&hbh,  g_hbh);
    cudaGetSymbolAddress((void**)&hbl,  g_hbl);

    __nv_bfloat16 *qh, *ql, *kh, *kl, *vh, *vl;
    cudaGetSymbolAddress((void**)&qh, g_qh);
    cudaGetSymbolAddress((void**)&ql, g_ql);
    cudaGetSymbolAddress((void**)&kh, g_kh);
    cudaGetSymbolAddress((void**)&kl, g_kl);
    cudaGetSymbolAddress((void**)&vh, g_vh);
    cudaGetSymbolAddress((void**)&vl, g_vl);

    __nv_bfloat16 *wqh,*wql,*wkh,*wkl,*wvh,*wvl,*woh,*wol,*w1h,*w1l,*w2h,*w2l;
    cudaGetSymbolAddress((void**)&wqh, g_wqt_h); cudaGetSymbolAddress((void**)&wql, g_wqt_l);
    cudaGetSymbolAddress((void**)&wkh, g_wkt_h); cudaGetSymbolAddress((void**)&wkl, g_wkt_l);
    cudaGetSymbolAddress((void**)&wvh, g_wvt_h); cudaGetSymbolAddress((void**)&wvl, g_wvt_l);
    cudaGetSymbolAddress((void**)&woh, g_wot_h); cudaGetSymbolAddress((void**)&wol, g_wot_l);
    cudaGetSymbolAddress((void**)&w1h, g_w1t_h); cudaGetSymbolAddress((void**)&w1l, g_w1t_l);
    cudaGetSymbolAddress((void**)&w2h, g_w2t_h); cudaGetSymbolAddress((void**)&w2l, g_w2t_l);

    cudaFuncSetAttribute(attn_kernel, cudaFuncAttributeMaxDynamicSharedMemorySize,
                         A4_BYTES);
    cudaFuncSetAttribute(qkv_mm, cudaFuncAttributeMaxDynamicSharedMemorySize, DSM_BYTES);
    cudaFuncSetAttribute(gemm_ksplit, cudaFuncAttributeMaxDynamicSharedMemorySize, DSM_BYTES);
    cudaFuncSetAttribute(gemm_mm<1,0,0,1>, cudaFuncAttributeMaxDynamicSharedMemorySize, DSM_BYTES);

    cudaMemcpyAsync(x, tokens, sizeof(float) * (size_t)BT * DIM,
                    cudaMemcpyDeviceToDevice, 0);

    // weight conversion
    {
        dim3 blk(32, 8);
        dim3 gdd(DIM / 32, DIM / 32, NL);
        wconv_kernel<<<gdd, blk>>>(Wq, wqh, wql, DIM, DIM);
        wconv_kernel<<<gdd, blk>>>(Wk, wkh, wkl, DIM, DIM);
        wconv_kernel<<<gdd, blk>>>(Wv, wvh, wvl, DIM, DIM);
        wconv_kernel<<<gdd, blk>>>(Wo, woh, wol, DIM, DIM);
        dim3 g1d(DFF / 32, DIM / 32, NL);
        wconv_kernel<<<g1d, blk>>>(W1, w1h, w1l, DIM, DFF);
        dim3 g2d(DIM / 32, DFF / 32, NL);
        wconv_kernel<<<g2d, blk>>>(W2, w2h, w2l, DFF, DIM);
    }

    dim3 gQKV(DIM / 128, BT / 128, 3);
    dim3 gKS (DIM / 128, BT / 128, 2);
    dim3 gF  (DFF / 128, BT / 128);
    dim3 gAtt(SEQ / QT, BATCH * NH);

    for (int l = 0; l < NL; l++) {
        size_t wofs  = (size_t)l * DIM * DIM;
        size_t w1ofs = (size_t)l * DIM * DFF;

        const float* pp0 = (l == 0) ? nullptr : p0;
        const float* pp1 = (l == 0) ? nullptr : p1;
        float* xo = (l == 0) ? nullptr : x;
        ln_kernel<<<BT, 256>>>(x, pp0, pp1, g1 + l * DIM, be1 + l * DIM,
                               xo, nullptr, xnh, xnl);

        qkv_mm<<<gQKV, 256, DSM_BYTES>>>(xnh, xnl,
                                         wqh + wofs, wql + wofs,
                                         wkh + wofs, wkl + wofs,
                                         wvh + wofs, wvl + wofs,
                                         bq + l * DIM, bk + l * DIM, bv + l * DIM,
                                         q, k, vh, vl);

        qkvprep_kernel<<<PREP_BLOCKS, 256>>>(q, k, qh, ql, kh, kl);

        attn_kernel<<<gAtt, 256, A4_BYTES>>>(qh, ql, kh, kl, vh, vl, atth, attl);

        gemm_ksplit<<<gKS, 256, DSM_BYTES>>>(atth, attl, woh + wofs, wol + wofs,
                                             bo + l * DIM, p0, p1, DIM, DIM);

        ln_kernel<<<BT, 256>>>(x, p0, p1, g2 + l * DIM, be2 + l * DIM,
                               x, nullptr, xnh, xnl);

        gemm_mm<1,0,0,1><<<gF, 256, DSM_BYTES>>>(xnh, xnl, w1h + w1ofs, w1l + w1ofs,
                                                 b1 + l * DFF, nullptr, nullptr, hbh, hbl,
                                                 DFF, DIM);

        gemm_ksplit<<<gKS, 256, DSM_BYTES>>>(hbh, hbl, w2h + w1ofs, w2l + w1ofs,
                                             b2 + l * DIM, p0, p1, DIM, DFF);
    }

    ln_kernel<<<BT, 256>>>(x, p0, p1, gf, bf, nullptr, (float*)d_out,
                           nullptr, nullptr);
}